// round 8
// baseline (speedup 1.0000x reference)
#include <cuda_runtime.h>
#include <math.h>

#define BB   128
#define NN   8192
#define MM   64
#define HID  512
#define OUTC 256
#define REPR 70
#define SEQW 63
#define NCHUNK 32           // 256 rows per chunk

// ---------------- scratch (device globals) ----------------
__device__ float g_kr[BB*MM];
__device__ float g_kw[BB*MM];
__device__ float g_par[BB*16];
__device__ float g_ae[BB*MM];
__device__ float g_aux[BB*4];               // 0:||ae||^2  1:ae.kr  2:S=sum(ww*wr)
__device__ float g_msum_part[NCHUNK*BB*MM];
__device__ float g_out_part [NCHUNK*BB*MM];
__device__ float g_dkw[BB*NN];
__device__ float g_dkr[BB*NN];
__device__ float g_n2 [BB*NN];
__device__ float g_dae[BB*NN];
__device__ float g_ww [BB*NN];
__device__ float g_wr [BB*NN];
__device__ float g_tmp [BB*NN];
__device__ float g_tmp2[BB*NN];
__device__ unsigned g_eadone[BB];           // zero-init; reset by k_addrR

__device__ __forceinline__ float lrelu(float v){ return (v>0.f)? v : 0.01f*v; }

// ---- block reductions ----
__device__ __forceinline__ float bredsum(float v, float* sred, int nw){
    const int lane = threadIdx.x & 31, wid = threadIdx.x >> 5;
    #pragma unroll
    for (int o=16;o>0;o>>=1) v += __shfl_xor_sync(0xffffffffu, v, o);
    if (lane==0) sred[wid]=v;
    __syncthreads();
    if (wid==0){
        float w = (lane<nw)? sred[lane] : 0.f;
        #pragma unroll
        for (int o=16;o>0;o>>=1) w += __shfl_xor_sync(0xffffffffu, w, o);
        if (lane==0) sred[0]=w;
    }
    __syncthreads();
    float r = sred[0];
    __syncthreads();
    return r;
}
__device__ __forceinline__ float bredmax(float v, float* sred, int nw){
    const int lane = threadIdx.x & 31, wid = threadIdx.x >> 5;
    #pragma unroll
    for (int o=16;o>0;o>>=1) v = fmaxf(v, __shfl_xor_sync(0xffffffffu, v, o));
    if (lane==0) sred[wid]=v;
    __syncthreads();
    if (wid==0){
        float w = (lane<nw)? sred[lane] : -1e30f;
        #pragma unroll
        for (int o=16;o>0;o>>=1) w = fmaxf(w, __shfl_xor_sync(0xffffffffu, w, o));
        if (lane==0) sred[0]=w;
    }
    __syncthreads();
    float r = sred[0];
    __syncthreads();
    return r;
}

// ---------------- fused controller ----------------
__global__ void __launch_bounds__(256) k_ctrl(
    const float* __restrict__ x,
    const float* __restrict__ W0, const float* __restrict__ b0,
    const float* __restrict__ W1, const float* __restrict__ b1,
    const float* __restrict__ Wc, const float* __restrict__ bc,
    const float* __restrict__ Wr, const float* __restrict__ br,
    const float* __restrict__ Ww, const float* __restrict__ bw,
    const float* __restrict__ wrp, const float* __restrict__ wwp)
{
    const int b = blockIdx.x;
    const int t = threadIdx.x;
    __shared__ float xs[SEQW+1];
    __shared__ float h0s[HID];
    __shared__ float h1s[HID];
    __shared__ float cs_[OUTC];
    __shared__ float rr[REPR];
    __shared__ float rw[REPR];
    __shared__ float sred[32];

    if (t < SEQW+1) xs[t] = x[b*(SEQW+1)+t];
    __syncthreads();

    {
        float a0 = b0[t], a1 = b0[t+256];
        #pragma unroll
        for (int i=0;i<SEQW+1;i++){
            float v = xs[i];
            a0 = fmaf(v, W0[i*HID + t],     a0);
            a1 = fmaf(v, W0[i*HID + t+256], a1);
        }
        h0s[t] = lrelu(a0); h0s[t+256] = lrelu(a1);
    }
    __syncthreads();
    {
        float a0 = b1[t], a1 = b1[t+256];
        #pragma unroll 8
        for (int i=0;i<HID;i++){
            float v = h0s[i];
            a0 = fmaf(v, W1[i*HID + t],     a0);
            a1 = fmaf(v, W1[i*HID + t+256], a1);
        }
        h1s[t] = lrelu(a0); h1s[t+256] = lrelu(a1);
    }
    __syncthreads();
    {
        float a0 = bc[t];
        #pragma unroll 8
        for (int i=0;i<HID;i++)
            a0 = fmaf(h1s[i], Wc[i*OUTC + t], a0);
        cs_[t] = lrelu(a0);
    }
    __syncthreads();
    if (t < REPR){
        float a = br[t];
        #pragma unroll 8
        for (int i=0;i<OUTC;i++) a = fmaf(cs_[i], Wr[i*REPR + t], a);
        rr[t] = a;
    } else if (t >= 128 && t < 128+REPR){
        const int j = t-128;
        float a = bw[j];
        #pragma unroll 8
        for (int i=0;i<OUTC;i++) a = fmaf(cs_[i], Ww[i*REPR + j], a);
        rw[j] = a;
    }
    __syncthreads();

    float vr = 0.f, vw = 0.f;
    if (t < MM){
        vr = rr[t]; vw = rw[t];
        g_kr[b*MM+t] = vr; g_kw[b*MM+t] = vw;
    }
    float nr = bredsum(vr*vr, sred, 8);
    float nw_ = bredsum(vw*vw, sred, 8);
    if (t==0){ g_par[b*16+12]=sqrtf(nr); g_par[b*16+13]=sqrtf(nw_); }

    const size_t base = (size_t)b*NN;
    float sr=0.f, sw=0.f;
    for (int n=t; n<NN; n+=256){ sr += wrp[base+n]; sw += wwp[base+n]; }
    sr = bredsum(sr, sred, 8);
    sw = bredsum(sw, sred, 8);
    if (t==0){ g_par[b*16+14]=1.f/sr; g_par[b*16+15]=1.f/sw; }

    if (t==0){
        float* p = &g_par[b*16];
        p[0] = fmaxf(rr[64],0.f)+1e-8f;
        p[1] = 1.f/(1.f+__expf(-rr[65]));
        {
            float m = fmaxf(rr[66], fmaxf(rr[67], rr[68]));
            float e0=__expf(rr[66]-m), e1=__expf(rr[67]-m), e2=__expf(rr[68]-m);
            float s=e0+e1+e2;
            p[2]=e0/s; p[3]=e1/s; p[4]=e2/s;
        }
        p[5] = fmaxf(rr[69],0.f)+1.f;
        p[6] = fmaxf(rw[64],0.f)+1e-8f;
        p[7] = 1.f/(1.f+__expf(-rw[65]));
        {
            float m = fmaxf(rw[66], fmaxf(rw[67], rw[68]));
            float e0=__expf(rw[66]-m), e1=__expf(rw[67]-m), e2=__expf(rw[68]-m);
            float s=e0+e1+e2;
            p[8]=e0/s; p[9]=e1/s; p[10]=e2/s;
        }
        p[11] = fmaxf(rw[69],0.f)+1.f;
    }
}

// ---------------- pass A: 4-lanes-per-row. dkw, n2, colsums ----------------
// grid (32, 128), 256 thr. warp: 8 rows/iter, 4 iters -> 256-row chunk covered by 8 warps.
__global__ void __launch_bounds__(256) k_passA(const float* __restrict__ bank)
{
    const int b = blockIdx.y;
    const int chunk = blockIdx.x;
    const int warp = threadIdx.x >> 5;
    const int lane = threadIdx.x & 31;
    const int sub4 = lane & 3;
    const int rowg = lane >> 2;
    const size_t bbase = (size_t)b * NN;
    const int coff = sub4*4;

    __shared__ float scs[MM];
    if (threadIdx.x < MM) scs[threadIdx.x] = 0.f;

    float4 kw4[4];
    #pragma unroll
    for (int i=0;i<4;i++) kw4[i] = *reinterpret_cast<const float4*>(&g_kw[b*MM + coff + i*16]);

    float4 cs[4];
    #pragma unroll
    for (int i=0;i<4;i++) cs[i] = make_float4(0.f,0.f,0.f,0.f);

    __syncthreads();

    #pragma unroll
    for (int it=0; it<4; it++){
        const int row = chunk*256 + it*64 + warp*8 + rowg;
        const float* rp = bank + (bbase + row)*MM + coff;
        float4 v[4];
        #pragma unroll
        for (int i=0;i<4;i++) v[i] = *reinterpret_cast<const float4*>(rp + i*16);
        float dkw = 0.f, nn = 0.f;
        #pragma unroll
        for (int i=0;i<4;i++){
            dkw = fmaf(v[i].x,kw4[i].x,dkw); dkw = fmaf(v[i].y,kw4[i].y,dkw);
            dkw = fmaf(v[i].z,kw4[i].z,dkw); dkw = fmaf(v[i].w,kw4[i].w,dkw);
            nn  = fmaf(v[i].x,v[i].x,nn);    nn  = fmaf(v[i].y,v[i].y,nn);
            nn  = fmaf(v[i].z,v[i].z,nn);    nn  = fmaf(v[i].w,v[i].w,nn);
            cs[i].x += v[i].x; cs[i].y += v[i].y; cs[i].z += v[i].z; cs[i].w += v[i].w;
        }
        dkw += __shfl_xor_sync(0xffffffffu, dkw, 1);
        dkw += __shfl_xor_sync(0xffffffffu, dkw, 2);
        nn  += __shfl_xor_sync(0xffffffffu, nn , 1);
        nn  += __shfl_xor_sync(0xffffffffu, nn , 2);
        if (sub4 == 0){
            g_dkw[bbase+row] = dkw;
            g_n2 [bbase+row] = nn;
        }
    }

    // colsum: reduce over row-groups (lanes sharing sub4), then smem atomics
    #pragma unroll
    for (int o=4;o<=16;o<<=1){
        #pragma unroll
        for (int i=0;i<4;i++){
            cs[i].x += __shfl_xor_sync(0xffffffffu, cs[i].x, o);
            cs[i].y += __shfl_xor_sync(0xffffffffu, cs[i].y, o);
            cs[i].z += __shfl_xor_sync(0xffffffffu, cs[i].z, o);
            cs[i].w += __shfl_xor_sync(0xffffffffu, cs[i].w, o);
        }
    }
    if (rowg == 0){
        #pragma unroll
        for (int i=0;i<4;i++){
            atomicAdd(&scs[i*16+coff+0], cs[i].x);
            atomicAdd(&scs[i*16+coff+1], cs[i].y);
            atomicAdd(&scs[i*16+coff+2], cs[i].z);
            atomicAdd(&scs[i*16+coff+3], cs[i].w);
        }
    }
    __syncthreads();
    if (threadIdx.x < MM)
        g_msum_part[(chunk*BB + b)*MM + threadIdx.x] = scs[threadIdx.x];
}

// ---------------- write addressing (global scratch) ----------------
__device__ void addr_write_global(int b, const float* __restrict__ wprev)
{
    __shared__ float sred[32];
    const int t = threadIdx.x;      // 256
    const size_t base = (size_t)b*NN;
    float* arr  = &g_tmp [base];
    float* arr2 = &g_tmp2[base];
    const float* p = &g_par[b*16];
    const float beta=p[6], gg=p[7], s0=p[8], s1=p[9], s2=p[10], gamma=p[11];
    const float nk=p[13], invs=p[15];

    float lmax = -1e30f;
    for (int i=0;i<32;i++){
        int n = t + i*256;
        float cosv = __fdividef(g_dkw[base+n], fmaxf(sqrtf(g_n2[base+n])*nk, 1e-8f));
        float tv = beta*cosv;
        arr[n]=tv;
        lmax = fmaxf(lmax, tv);
    }
    const float bmax = bredmax(lmax, sred, 8);

    float lsum=0.f;
    for (int i=0;i<32;i++){
        int n=t+i*256;
        float e = __expf(arr[n]-bmax);
        arr[n]=e; lsum+=e;
    }
    const float invsum = __fdividef(1.f, bredsum(lsum, sred, 8));

    for (int i=0;i<32;i++){
        int n=t+i*256;
        float wc  = arr[n]*invsum;
        arr[n] = gg*wc + (1.f-gg)*wprev[base+n]*invs;
    }
    __syncthreads();

    float lps=0.f;
    for (int i=0;i<32;i++){
        int n=t+i*256;
        float ws = s0*arr[(n+NN-1)&(NN-1)] + s1*arr[n] + s2*arr[(n+1)&(NN-1)];
        float wp = __powf(ws, gamma);
        arr2[n]=wp; lps+=wp;
    }
    const float invp = __fdividef(1.f, bredsum(lps, sred, 8));

    for (int i=0;i<32;i++){
        int n=t+i*256;
        g_ww[base+n] = arr2[n]*invp;
    }
}

// ---------------- ea body (256 threads) ----------------
__device__ void ea_body(int b, const float* __restrict__ Wea, const float* __restrict__ bea)
{
    __shared__ float ma[MM], kws[MM], eas[2*MM], sred[32];
    const int t = threadIdx.x;
    if (t<MM){
        float s = 0.f;
        #pragma unroll 8
        for (int c=0;c<NCHUNK;c++) s += g_msum_part[(c*BB + b)*MM + t];
        ma[t]  = s * (1.f/(float)NN);
        kws[t] = g_kw[b*MM+t];
    }
    __syncthreads();
    if (t < 2*MM){
        float acc = bea[t];
        #pragma unroll 8
        for (int i=0;i<MM;i++)  acc = fmaf(ma[i],  Wea[i*(2*MM)+t],      acc);
        #pragma unroll 8
        for (int i=0;i<MM;i++)  acc = fmaf(kws[i], Wea[(MM+i)*(2*MM)+t], acc);
        eas[t]=acc;
    }
    __syncthreads();
    float ae=0.f, krv=0.f;
    if (t<MM){
        float e = 1.f/(1.f+__expf(-eas[t]));
        ae = eas[MM+t]-e;
        g_ae[b*MM+t]=ae;
        krv = g_kr[b*MM+t];
    }
    float a2 = bredsum(ae*ae, sred, 8);
    float ak = bredsum(ae*krv, sred, 8);
    if (t==0){
        g_aux[b*4+0]=a2; g_aux[b*4+1]=ak;
        __threadfence();
        atomicExch(&g_eadone[b], 1u);
    }
}

// ---------------- fused: addrW [0,128) + ea [128,256) + passB (spin on ea) ----------------
__global__ void __launch_bounds__(256) k_fusedB(const float* __restrict__ bank,
                                                const float* __restrict__ wwp,
                                                const float* __restrict__ Wea,
                                                const float* __restrict__ bea)
{
    if (blockIdx.x < BB){ addr_write_global(blockIdx.x, wwp); return; }
    if (blockIdx.x < 2*BB){ ea_body(blockIdx.x - BB, Wea, bea); return; }

    const int u = blockIdx.x - 2*BB;
    const int b = u >> 5, chunk = u & 31;
    const int warp = threadIdx.x >> 5;
    const int lane = threadIdx.x & 31;
    const int sub4 = lane & 3;
    const int rowg = lane >> 2;
    const size_t bbase = (size_t)b * NN;
    const int coff = sub4*4;

    // wait for this batch's ae
    if (threadIdx.x == 0){
        while (atomicAdd(&g_eadone[b], 0u) == 0u) __nanosleep(200);
    }
    __syncthreads();
    __threadfence();

    float4 ae4[4], kr4[4];
    #pragma unroll
    for (int i=0;i<4;i++){
        ae4[i] = *reinterpret_cast<const float4*>(&g_ae[b*MM + coff + i*16]);
        kr4[i] = *reinterpret_cast<const float4*>(&g_kr[b*MM + coff + i*16]);
    }

    #pragma unroll
    for (int it=0; it<4; it++){
        const int row = chunk*256 + it*64 + warp*8 + rowg;
        const float* rp = bank + (bbase + row)*MM + coff;
        float4 v[4];
        #pragma unroll
        for (int i=0;i<4;i++) v[i] = *reinterpret_cast<const float4*>(rp + i*16);
        float d = 0.f, dk = 0.f;
        #pragma unroll
        for (int i=0;i<4;i++){
            d  = fmaf(v[i].x,ae4[i].x,d);  d  = fmaf(v[i].y,ae4[i].y,d);
            d  = fmaf(v[i].z,ae4[i].z,d);  d  = fmaf(v[i].w,ae4[i].w,d);
            dk = fmaf(v[i].x,kr4[i].x,dk); dk = fmaf(v[i].y,kr4[i].y,dk);
            dk = fmaf(v[i].z,kr4[i].z,dk); dk = fmaf(v[i].w,kr4[i].w,dk);
        }
        d  += __shfl_xor_sync(0xffffffffu, d , 1);
        d  += __shfl_xor_sync(0xffffffffu, d , 2);
        dk += __shfl_xor_sync(0xffffffffu, dk, 1);
        dk += __shfl_xor_sync(0xffffffffu, dk, 2);
        if (sub4 == 0){
            g_dae[bbase+row] = d;
            g_dkr[bbase+row] = dk;
        }
    }
}

// ---------------- read addressing (1024 threads) + eadone reset ----------------
__global__ void __launch_bounds__(1024) k_addrR(const float* __restrict__ wrp)
{
    __shared__ float arr[NN];
    __shared__ float sred[32];
    const int b = blockIdx.x;
    const int t = threadIdx.x;
    if (t==0) g_eadone[b] = 0u;     // reset for next graph replay
    const size_t base = (size_t)b*NN;
    const float* p = &g_par[b*16];
    const float beta=p[0], gg=p[1], s0=p[2], s1=p[3], s2=p[4], gamma=p[5];
    const float nk=p[12], invs=p[14];
    const float ae2=g_aux[b*4], aekr=g_aux[b*4+1];

    float lmax = -1e30f;
    #pragma unroll
    for (int i=0;i<8;i++){
        int n = t + i*1024;
        float w  = g_ww[base+n];
        float d  = g_dkr[base+n] + w*aekr;
        float nn = fmaxf(g_n2[base+n] + 2.f*w*g_dae[base+n] + w*w*ae2, 0.f);
        float cosv = __fdividef(d, fmaxf(sqrtf(nn)*nk, 1e-8f));
        float tv = beta*cosv;
        arr[n]=tv;
        lmax = fmaxf(lmax, tv);
    }
    const float bmax = bredmax(lmax, sred, 32);

    float lsum=0.f;
    #pragma unroll
    for (int i=0;i<8;i++){
        int n=t+i*1024;
        float e = __expf(arr[n]-bmax);
        arr[n]=e; lsum+=e;
    }
    const float invsum = __fdividef(1.f, bredsum(lsum, sred, 32));

    #pragma unroll
    for (int i=0;i<8;i++){
        int n=t+i*1024;
        float wc  = arr[n]*invsum;
        arr[n] = gg*wc + (1.f-gg)*wrp[base+n]*invs;
    }
    __syncthreads();

    float wp_loc[8];
    float lps=0.f;
    #pragma unroll
    for (int i=0;i<8;i++){
        int n=t+i*1024;
        float ws = s0*arr[(n+NN-1)&(NN-1)] + s1*arr[n] + s2*arr[(n+1)&(NN-1)];
        float wp = __powf(ws, gamma);
        wp_loc[i]=wp; lps+=wp;
    }
    const float invp = __fdividef(1.f, bredsum(lps, sred, 32));

    float lS=0.f;
    #pragma unroll
    for (int i=0;i<8;i++){
        int n=t+i*1024;
        float w = wp_loc[i]*invp;
        g_wr[base+n]=w;
        lS += g_ww[base+n]*w;
    }
    float S = bredsum(lS, sred, 32);
    if (t==0) g_aux[b*4+2]=S;
}

// ---------------- pass C: 4-lanes-per-row weighted read ----------------
__global__ void __launch_bounds__(256) k_passC(const float* __restrict__ bank)
{
    const int b = blockIdx.y;
    const int chunk = blockIdx.x;
    const int warp = threadIdx.x >> 5;
    const int lane = threadIdx.x & 31;
    const int sub4 = lane & 3;
    const int rowg = lane >> 2;
    const size_t bbase = (size_t)b * NN;
    const int coff = sub4*4;

    __shared__ float scs[MM];
    if (threadIdx.x < MM) scs[threadIdx.x] = 0.f;

    float4 o4[4];
    #pragma unroll
    for (int i=0;i<4;i++) o4[i] = make_float4(0.f,0.f,0.f,0.f);

    __syncthreads();

    #pragma unroll
    for (int it=0; it<4; it++){
        const int row = chunk*256 + it*64 + warp*8 + rowg;
        const float* rp = bank + (bbase + row)*MM + coff;
        const float wr = g_wr[bbase+row];
        float4 v[4];
        #pragma unroll
        for (int i=0;i<4;i++) v[i] = *reinterpret_cast<const float4*>(rp + i*16);
        #pragma unroll
        for (int i=0;i<4;i++){
            o4[i].x = fmaf(v[i].x, wr, o4[i].x);
            o4[i].y = fmaf(v[i].y, wr, o4[i].y);
            o4[i].z = fmaf(v[i].z, wr, o4[i].z);
            o4[i].w = fmaf(v[i].w, wr, o4[i].w);
        }
    }

    #pragma unroll
    for (int o=4;o<=16;o<<=1){
        #pragma unroll
        for (int i=0;i<4;i++){
            o4[i].x += __shfl_xor_sync(0xffffffffu, o4[i].x, o);
            o4[i].y += __shfl_xor_sync(0xffffffffu, o4[i].y, o);
            o4[i].z += __shfl_xor_sync(0xffffffffu, o4[i].z, o);
            o4[i].w += __shfl_xor_sync(0xffffffffu, o4[i].w, o);
        }
    }
    if (rowg == 0){
        #pragma unroll
        for (int i=0;i<4;i++){
            atomicAdd(&scs[i*16+coff+0], o4[i].x);
            atomicAdd(&scs[i*16+coff+1], o4[i].y);
            atomicAdd(&scs[i*16+coff+2], o4[i].z);
            atomicAdd(&scs[i*16+coff+3], o4[i].w);
        }
    }
    __syncthreads();
    if (threadIdx.x < MM)
        g_out_part[(chunk*BB + b)*MM + threadIdx.x] = scs[threadIdx.x];
}

// ---------------- final head ----------------
__global__ void k_final(const float* __restrict__ Wsp, const float* __restrict__ bsp,
                        const float* __restrict__ Wo,  const float* __restrict__ bo,
                        float* __restrict__ out)
{
    const int b=blockIdx.x, t=threadIdx.x;   // 128
    __shared__ float om[MM], seq[HID];
    if (t<MM){
        float s = 0.f;
        #pragma unroll 8
        for (int c=0;c<NCHUNK;c++) s += g_out_part[(c*BB + b)*MM + t];
        om[t] = s + g_aux[b*4+2]*g_ae[b*MM+t];
    }
    __syncthreads();
    for (int j=t; j<HID; j+=128){
        float a = bsp[j];
        #pragma unroll 8
        for (int i=0;i<MM;i++) a = fmaf(om[i], Wsp[i*HID+j], a);
        seq[j] = lrelu(a);
    }
    __syncthreads();
    if (t<SEQW){
        float a = bo[t];
        for (int i=0;i<HID;i++) a = fmaf(seq[i], Wo[i*SEQW+t], a);
        out[b*SEQW+t] = 1.f/(1.f+__expf(-a));
    }
}

// ---------------- launch ----------------
extern "C" void kernel_launch(void* const* d_in, const int* in_sizes, int n_in,
                              void* d_out, int out_size)
{
    const float* x    = (const float*)d_in[0];
    const float* bank = (const float*)d_in[1];
    const float* wrp  = (const float*)d_in[2];
    const float* wwp  = (const float*)d_in[3];
    const float* W0   = (const float*)d_in[4];
    const float* b0   = (const float*)d_in[5];
    const float* W1   = (const float*)d_in[6];
    const float* b1   = (const float*)d_in[7];
    const float* Wc   = (const float*)d_in[8];
    const float* bc   = (const float*)d_in[9];
    const float* Wr   = (const float*)d_in[10];
    const float* br   = (const float*)d_in[11];
    const float* Ww   = (const float*)d_in[12];
    const float* bw   = (const float*)d_in[13];
    const float* Wea  = (const float*)d_in[14];
    const float* bea  = (const float*)d_in[15];
    const float* Wsp  = (const float*)d_in[16];
    const float* bsp  = (const float*)d_in[17];
    const float* Wo   = (const float*)d_in[18];
    const float* bo   = (const float*)d_in[19];
    float* out = (float*)d_out;

    k_ctrl<<<BB, 256>>>(x, W0,b0, W1,b1, Wc,bc, Wr,br, Ww,bw, wrp, wwp);
    k_passA<<<dim3(NCHUNK, BB), 256>>>(bank);
    k_fusedB<<<2*BB + NCHUNK*BB, 256>>>(bank, wwp, Wea, bea);  // addrW + ea + passB
    k_addrR<<<BB, 1024>>>(wrp);
    k_passC<<<dim3(NCHUNK, BB), 256>>>(bank);
    k_final<<<BB, 128>>>(Wsp, bsp, Wo, bo, out);
}

// round 9
// speedup vs baseline: 1.0628x; 1.0628x over previous
#include <cuda_runtime.h>
#include <math.h>

#define BB   128
#define NN   8192
#define MM   64
#define HID  512
#define OUTC 256
#define REPR 70
#define SEQW 63
#define NCHUNK 32           // 256 rows per chunk

// ---------------- scratch (device globals) ----------------
__device__ float g_kr[BB*MM];
__device__ float g_kw[BB*MM];
__device__ float g_par[BB*16];
__device__ float g_ae[BB*MM];
__device__ float g_aux[BB*4];               // 0:||ae||^2  1:ae.kr  2:S
__device__ float g_msum_part[NCHUNK*BB*MM];
__device__ float g_out_part [NCHUNK*BB*MM];
__device__ float g_dkw[BB*NN];
__device__ float g_dkr[BB*NN];
__device__ float g_n2 [BB*NN];
__device__ float g_dae[BB*NN];
__device__ float g_wr [BB*NN];
__device__ unsigned g_eadone[BB];           // zero-init; reset each replay by k_addrWR

__device__ __forceinline__ float lrelu(float v){ return (v>0.f)? v : 0.01f*v; }

// ---- block reductions ----
__device__ __forceinline__ float bredsum(float v, float* sred, int nw){
    const int lane = threadIdx.x & 31, wid = threadIdx.x >> 5;
    #pragma unroll
    for (int o=16;o>0;o>>=1) v += __shfl_xor_sync(0xffffffffu, v, o);
    if (lane==0) sred[wid]=v;
    __syncthreads();
    if (wid==0){
        float w = (lane<nw)? sred[lane] : 0.f;
        #pragma unroll
        for (int o=16;o>0;o>>=1) w += __shfl_xor_sync(0xffffffffu, w, o);
        if (lane==0) sred[0]=w;
    }
    __syncthreads();
    float r = sred[0];
    __syncthreads();
    return r;
}
__device__ __forceinline__ float bredmax(float v, float* sred, int nw){
    const int lane = threadIdx.x & 31, wid = threadIdx.x >> 5;
    #pragma unroll
    for (int o=16;o>0;o>>=1) v = fmaxf(v, __shfl_xor_sync(0xffffffffu, v, o));
    if (lane==0) sred[wid]=v;
    __syncthreads();
    if (wid==0){
        float w = (lane<nw)? sred[lane] : -1e30f;
        #pragma unroll
        for (int o=16;o>0;o>>=1) w = fmaxf(w, __shfl_xor_sync(0xffffffffu, w, o));
        if (lane==0) sred[0]=w;
    }
    __syncthreads();
    float r = sred[0];
    __syncthreads();
    return r;
}

// ---------------- controller body (256 threads) ----------------
__device__ void ctrl_body(int b,
    const float* __restrict__ x,
    const float* __restrict__ W0, const float* __restrict__ b0,
    const float* __restrict__ W1, const float* __restrict__ b1,
    const float* __restrict__ Wc, const float* __restrict__ bc,
    const float* __restrict__ Wr, const float* __restrict__ br,
    const float* __restrict__ Ww, const float* __restrict__ bw,
    const float* __restrict__ wrp, const float* __restrict__ wwp)
{
    const int t = threadIdx.x;
    __shared__ float xs[SEQW+1];
    __shared__ float h0s[HID];
    __shared__ float h1s[HID];
    __shared__ float cs_[OUTC];
    __shared__ float rr[REPR];
    __shared__ float rw[REPR];
    __shared__ float sred[32];

    if (t < SEQW+1) xs[t] = x[b*(SEQW+1)+t];
    __syncthreads();
    {
        float a0 = b0[t], a1 = b0[t+256];
        #pragma unroll
        for (int i=0;i<SEQW+1;i++){
            float v = xs[i];
            a0 = fmaf(v, W0[i*HID + t],     a0);
            a1 = fmaf(v, W0[i*HID + t+256], a1);
        }
        h0s[t] = lrelu(a0); h0s[t+256] = lrelu(a1);
    }
    __syncthreads();
    {
        float a0 = b1[t], a1 = b1[t+256];
        #pragma unroll 8
        for (int i=0;i<HID;i++){
            float v = h0s[i];
            a0 = fmaf(v, W1[i*HID + t],     a0);
            a1 = fmaf(v, W1[i*HID + t+256], a1);
        }
        h1s[t] = lrelu(a0); h1s[t+256] = lrelu(a1);
    }
    __syncthreads();
    {
        float a0 = bc[t];
        #pragma unroll 8
        for (int i=0;i<HID;i++)
            a0 = fmaf(h1s[i], Wc[i*OUTC + t], a0);
        cs_[t] = lrelu(a0);
    }
    __syncthreads();
    if (t < REPR){
        float a = br[t];
        #pragma unroll 8
        for (int i=0;i<OUTC;i++) a = fmaf(cs_[i], Wr[i*REPR + t], a);
        rr[t] = a;
    } else if (t >= 128 && t < 128+REPR){
        const int j = t-128;
        float a = bw[j];
        #pragma unroll 8
        for (int i=0;i<OUTC;i++) a = fmaf(cs_[i], Ww[i*REPR + j], a);
        rw[j] = a;
    }
    __syncthreads();

    float vr = 0.f, vw = 0.f;
    if (t < MM){
        vr = rr[t]; vw = rw[t];
        g_kr[b*MM+t] = vr; g_kw[b*MM+t] = vw;
    }
    float nr = bredsum(vr*vr, sred, 8);
    float nw_ = bredsum(vw*vw, sred, 8);
    if (t==0){ g_par[b*16+12]=sqrtf(nr); g_par[b*16+13]=sqrtf(nw_); }

    const size_t base = (size_t)b*NN;
    float sr=0.f, sw=0.f;
    for (int n=t; n<NN; n+=256){ sr += wrp[base+n]; sw += wwp[base+n]; }
    sr = bredsum(sr, sred, 8);
    sw = bredsum(sw, sred, 8);
    if (t==0){ g_par[b*16+14]=1.f/sr; g_par[b*16+15]=1.f/sw; }

    if (t==0){
        float* p = &g_par[b*16];
        p[0] = fmaxf(rr[64],0.f)+1e-8f;
        p[1] = 1.f/(1.f+__expf(-rr[65]));
        {
            float m = fmaxf(rr[66], fmaxf(rr[67], rr[68]));
            float e0=__expf(rr[66]-m), e1=__expf(rr[67]-m), e2=__expf(rr[68]-m);
            float s=e0+e1+e2;
            p[2]=e0/s; p[3]=e1/s; p[4]=e2/s;
        }
        p[5] = fmaxf(rr[69],0.f)+1.f;
        p[6] = fmaxf(rw[64],0.f)+1e-8f;
        p[7] = 1.f/(1.f+__expf(-rw[65]));
        {
            float m = fmaxf(rw[66], fmaxf(rw[67], rw[68]));
            float e0=__expf(rw[66]-m), e1=__expf(rw[67]-m), e2=__expf(rw[68]-m);
            float s=e0+e1+e2;
            p[8]=e0/s; p[9]=e1/s; p[10]=e2/s;
        }
        p[11] = fmaxf(rw[69],0.f)+1.f;
    }
}

// ---------------- k1: ctrl (blocks 0..127) + passA-lite (n2 + colsums) ----------------
__global__ void __launch_bounds__(256) k_ctrlA(const float* __restrict__ bank,
    const float* __restrict__ x,
    const float* __restrict__ W0, const float* __restrict__ b0,
    const float* __restrict__ W1, const float* __restrict__ b1,
    const float* __restrict__ Wc, const float* __restrict__ bc,
    const float* __restrict__ Wr, const float* __restrict__ br,
    const float* __restrict__ Ww, const float* __restrict__ bw,
    const float* __restrict__ wrp, const float* __restrict__ wwp)
{
    if (blockIdx.x < BB){
        ctrl_body(blockIdx.x, x, W0,b0, W1,b1, Wc,bc, Wr,br, Ww,bw, wrp, wwp);
        return;
    }
    const int u = blockIdx.x - BB;
    const int b = u >> 5, chunk = u & 31;
    const int warp = threadIdx.x >> 5;
    const int lane = threadIdx.x & 31;
    const int sub4 = lane & 3;
    const int rowg = lane >> 2;
    const size_t bbase = (size_t)b * NN;
    const int coff = sub4*4;

    __shared__ float scs[MM];
    if (threadIdx.x < MM) scs[threadIdx.x] = 0.f;

    float4 cs[4];
    #pragma unroll
    for (int i=0;i<4;i++) cs[i] = make_float4(0.f,0.f,0.f,0.f);
    __syncthreads();

    #pragma unroll
    for (int it=0; it<4; it++){
        const int row = chunk*256 + it*64 + warp*8 + rowg;
        const float* rp = bank + (bbase + row)*MM + coff;
        float4 v[4];
        #pragma unroll
        for (int i=0;i<4;i++) v[i] = *reinterpret_cast<const float4*>(rp + i*16);
        float nn = 0.f;
        #pragma unroll
        for (int i=0;i<4;i++){
            nn  = fmaf(v[i].x,v[i].x,nn); nn = fmaf(v[i].y,v[i].y,nn);
            nn  = fmaf(v[i].z,v[i].z,nn); nn = fmaf(v[i].w,v[i].w,nn);
            cs[i].x += v[i].x; cs[i].y += v[i].y; cs[i].z += v[i].z; cs[i].w += v[i].w;
        }
        nn += __shfl_xor_sync(0xffffffffu, nn, 1);
        nn += __shfl_xor_sync(0xffffffffu, nn, 2);
        if (sub4 == 0) g_n2[bbase+row] = nn;
    }
    #pragma unroll
    for (int o=4;o<=16;o<<=1){
        #pragma unroll
        for (int i=0;i<4;i++){
            cs[i].x += __shfl_xor_sync(0xffffffffu, cs[i].x, o);
            cs[i].y += __shfl_xor_sync(0xffffffffu, cs[i].y, o);
            cs[i].z += __shfl_xor_sync(0xffffffffu, cs[i].z, o);
            cs[i].w += __shfl_xor_sync(0xffffffffu, cs[i].w, o);
        }
    }
    if (rowg == 0){
        #pragma unroll
        for (int i=0;i<4;i++){
            atomicAdd(&scs[i*16+coff+0], cs[i].x);
            atomicAdd(&scs[i*16+coff+1], cs[i].y);
            atomicAdd(&scs[i*16+coff+2], cs[i].z);
            atomicAdd(&scs[i*16+coff+3], cs[i].w);
        }
    }
    __syncthreads();
    if (threadIdx.x < MM)
        g_msum_part[(chunk*BB + b)*MM + threadIdx.x] = scs[threadIdx.x];
}

// ---------------- ea body (256 threads) ----------------
__device__ void ea_body(int b, const float* __restrict__ Wea, const float* __restrict__ bea)
{
    __shared__ float ma[MM], kws[MM], eas[2*MM], sred[32];
    const int t = threadIdx.x;
    if (t<MM){
        float s = 0.f;
        #pragma unroll 8
        for (int c=0;c<NCHUNK;c++) s += g_msum_part[(c*BB + b)*MM + t];
        ma[t]  = s * (1.f/(float)NN);
        kws[t] = g_kw[b*MM+t];
    }
    __syncthreads();
    if (t < 2*MM){
        float acc = bea[t];
        #pragma unroll 8
        for (int i=0;i<MM;i++)  acc = fmaf(ma[i],  Wea[i*(2*MM)+t],      acc);
        #pragma unroll 8
        for (int i=0;i<MM;i++)  acc = fmaf(kws[i], Wea[(MM+i)*(2*MM)+t], acc);
        eas[t]=acc;
    }
    __syncthreads();
    float ae=0.f, krv=0.f;
    if (t<MM){
        float e = 1.f/(1.f+__expf(-eas[t]));
        ae = eas[MM+t]-e;
        g_ae[b*MM+t]=ae;
        krv = g_kr[b*MM+t];
    }
    float a2 = bredsum(ae*ae, sred, 8);
    float ak = bredsum(ae*krv, sred, 8);
    if (t==0){
        g_aux[b*4+0]=a2; g_aux[b*4+1]=ak;
        __threadfence();
        atomicExch(&g_eadone[b], 1u);
    }
}

// ---------------- k2: ea (blocks 0..127) + passB (dkw, dkr, dae; 8-lanes-per-row) ----------------
__global__ void __launch_bounds__(256) k_fusedB(const float* __restrict__ bank,
                                                const float* __restrict__ Wea,
                                                const float* __restrict__ bea)
{
    if (blockIdx.x < BB){ ea_body(blockIdx.x, Wea, bea); return; }

    const int u = blockIdx.x - BB;
    const int b = u >> 5, chunk = u & 31;
    const int warp = threadIdx.x >> 5;
    const int lane = threadIdx.x & 31;
    const int sub8 = lane & 7;
    const int rowg = lane >> 3;          // 4 rows per warp-iter
    const size_t bbase = (size_t)b * NN;
    const int coff = sub8*8;             // 8 floats per lane

    if (threadIdx.x == 0){
        while (atomicAdd(&g_eadone[b], 0u) == 0u) __nanosleep(200);
    }
    __syncthreads();
    __threadfence();

    const float4 aeA = *reinterpret_cast<const float4*>(&g_ae[b*MM + coff]);
    const float4 aeB = *reinterpret_cast<const float4*>(&g_ae[b*MM + coff + 4]);
    const float4 krA = *reinterpret_cast<const float4*>(&g_kr[b*MM + coff]);
    const float4 krB = *reinterpret_cast<const float4*>(&g_kr[b*MM + coff + 4]);
    const float4 kwA = *reinterpret_cast<const float4*>(&g_kw[b*MM + coff]);
    const float4 kwB = *reinterpret_cast<const float4*>(&g_kw[b*MM + coff + 4]);

    #pragma unroll
    for (int it=0; it<8; it++){
        const int row = chunk*256 + it*32 + warp*4 + rowg;
        const float* rp = bank + (bbase + row)*MM + coff;
        const float4 v0 = *reinterpret_cast<const float4*>(rp);
        const float4 v1 = *reinterpret_cast<const float4*>(rp + 4);
        float dw=0.f, dk=0.f, da=0.f;
        dw=fmaf(v0.x,kwA.x,dw); dw=fmaf(v0.y,kwA.y,dw); dw=fmaf(v0.z,kwA.z,dw); dw=fmaf(v0.w,kwA.w,dw);
        dw=fmaf(v1.x,kwB.x,dw); dw=fmaf(v1.y,kwB.y,dw); dw=fmaf(v1.z,kwB.z,dw); dw=fmaf(v1.w,kwB.w,dw);
        dk=fmaf(v0.x,krA.x,dk); dk=fmaf(v0.y,krA.y,dk); dk=fmaf(v0.z,krA.z,dk); dk=fmaf(v0.w,krA.w,dk);
        dk=fmaf(v1.x,krB.x,dk); dk=fmaf(v1.y,krB.y,dk); dk=fmaf(v1.z,krB.z,dk); dk=fmaf(v1.w,krB.w,dk);
        da=fmaf(v0.x,aeA.x,da); da=fmaf(v0.y,aeA.y,da); da=fmaf(v0.z,aeA.z,da); da=fmaf(v0.w,aeA.w,da);
        da=fmaf(v1.x,aeB.x,da); da=fmaf(v1.y,aeB.y,da); da=fmaf(v1.z,aeB.z,da); da=fmaf(v1.w,aeB.w,da);
        #pragma unroll
        for (int o=1;o<8;o<<=1){
            dw += __shfl_xor_sync(0xffffffffu, dw, o);
            dk += __shfl_xor_sync(0xffffffffu, dk, o);
            da += __shfl_xor_sync(0xffffffffu, da, o);
        }
        if (sub8 == 0){
            g_dkw[bbase+row] = dw;
            g_dkr[bbase+row] = dk;
            g_dae[bbase+row] = da;
        }
    }
}

// ---------------- k3: fused addrW + addrR (1024 threads, ww kept in registers) ----------------
__global__ void __launch_bounds__(1024) k_addrWR(const float* __restrict__ wwp,
                                                 const float* __restrict__ wrp)
{
    __shared__ float arr[NN];
    __shared__ float sred[32];
    const int b = blockIdx.x;
    const int t = threadIdx.x;
    if (t==0) g_eadone[b] = 0u;     // reset for next graph replay
    const size_t base = (size_t)b*NN;
    const float* p = &g_par[b*16];

    float ww_loc[8];

    // ======= WRITE addressing =======
    {
        const float beta=p[6], gg=p[7], s0=p[8], s1=p[9], s2=p[10], gamma=p[11];
        const float nk=p[13], invs=p[15];
        float lmax = -1e30f;
        #pragma unroll
        for (int i=0;i<8;i++){
            int n = t + i*1024;
            float cosv = __fdividef(g_dkw[base+n], fmaxf(sqrtf(g_n2[base+n])*nk, 1e-8f));
            float tv = beta*cosv;
            arr[n]=tv;
            lmax = fmaxf(lmax, tv);
        }
        const float bmax = bredmax(lmax, sred, 32);
        float lsum=0.f;
        #pragma unroll
        for (int i=0;i<8;i++){
            int n=t+i*1024;
            float e = __expf(arr[n]-bmax);
            arr[n]=e; lsum+=e;
        }
        const float invsum = __fdividef(1.f, bredsum(lsum, sred, 32));
        #pragma unroll
        for (int i=0;i<8;i++){
            int n=t+i*1024;
            float wc  = arr[n]*invsum;
            arr[n] = gg*wc + (1.f-gg)*wwp[base+n]*invs;
        }
        __syncthreads();
        float lps=0.f;
        #pragma unroll
        for (int i=0;i<8;i++){
            int n=t+i*1024;
            float ws = s0*arr[(n+NN-1)&(NN-1)] + s1*arr[n] + s2*arr[(n+1)&(NN-1)];
            float wp = __powf(ws, gamma);
            ww_loc[i]=wp; lps+=wp;
        }
        const float invp = __fdividef(1.f, bredsum(lps, sred, 32));
        #pragma unroll
        for (int i=0;i<8;i++) ww_loc[i] *= invp;
    }
    __syncthreads();   // arr reuse barrier

    // ======= READ addressing (virtual new_bank via rank-1 algebra) =======
    {
        const float beta=p[0], gg=p[1], s0=p[2], s1=p[3], s2=p[4], gamma=p[5];
        const float nk=p[12], invs=p[14];
        const float ae2=g_aux[b*4], aekr=g_aux[b*4+1];
        float lmax = -1e30f;
        #pragma unroll
        for (int i=0;i<8;i++){
            int n = t + i*1024;
            float w  = ww_loc[i];
            float d  = g_dkr[base+n] + w*aekr;
            float nn = fmaxf(g_n2[base+n] + 2.f*w*g_dae[base+n] + w*w*ae2, 0.f);
            float cosv = __fdividef(d, fmaxf(sqrtf(nn)*nk, 1e-8f));
            float tv = beta*cosv;
            arr[n]=tv;
            lmax = fmaxf(lmax, tv);
        }
        const float bmax = bredmax(lmax, sred, 32);
        float lsum=0.f;
        #pragma unroll
        for (int i=0;i<8;i++){
            int n=t+i*1024;
            float e = __expf(arr[n]-bmax);
            arr[n]=e; lsum+=e;
        }
        const float invsum = __fdividef(1.f, bredsum(lsum, sred, 32));
        #pragma unroll
        for (int i=0;i<8;i++){
            int n=t+i*1024;
            float wc  = arr[n]*invsum;
            arr[n] = gg*wc + (1.f-gg)*wrp[base+n]*invs;
        }
        __syncthreads();
        float wp_loc[8];
        float lps=0.f;
        #pragma unroll
        for (int i=0;i<8;i++){
            int n=t+i*1024;
            float ws = s0*arr[(n+NN-1)&(NN-1)] + s1*arr[n] + s2*arr[(n+1)&(NN-1)];
            float wp = __powf(ws, gamma);
            wp_loc[i]=wp; lps+=wp;
        }
        const float invp = __fdividef(1.f, bredsum(lps, sred, 32));
        float lS=0.f;
        #pragma unroll
        for (int i=0;i<8;i++){
            int n=t+i*1024;
            float w = wp_loc[i]*invp;
            g_wr[base+n]=w;
            lS += ww_loc[i]*w;
        }
        float S = bredsum(lS, sred, 32);
        if (t==0) g_aux[b*4+2]=S;
    }
}

// ---------------- k4: pass C (weighted read) ----------------
__global__ void __launch_bounds__(256) k_passC(const float* __restrict__ bank)
{
    const int b = blockIdx.y;
    const int chunk = blockIdx.x;
    const int warp = threadIdx.x >> 5;
    const int lane = threadIdx.x & 31;
    const int sub4 = lane & 3;
    const int rowg = lane >> 2;
    const size_t bbase = (size_t)b * NN;
    const int coff = sub4*4;

    __shared__ float scs[MM];
    if (threadIdx.x < MM) scs[threadIdx.x] = 0.f;

    float4 o4[4];
    #pragma unroll
    for (int i=0;i<4;i++) o4[i] = make_float4(0.f,0.f,0.f,0.f);
    __syncthreads();

    #pragma unroll
    for (int it=0; it<4; it++){
        const int row = chunk*256 + it*64 + warp*8 + rowg;
        const float* rp = bank + (bbase + row)*MM + coff;
        const float wr = g_wr[bbase+row];
        float4 v[4];
        #pragma unroll
        for (int i=0;i<4;i++) v[i] = *reinterpret_cast<const float4*>(rp + i*16);
        #pragma unroll
        for (int i=0;i<4;i++){
            o4[i].x = fmaf(v[i].x, wr, o4[i].x);
            o4[i].y = fmaf(v[i].y, wr, o4[i].y);
            o4[i].z = fmaf(v[i].z, wr, o4[i].z);
            o4[i].w = fmaf(v[i].w, wr, o4[i].w);
        }
    }
    #pragma unroll
    for (int o=4;o<=16;o<<=1){
        #pragma unroll
        for (int i=0;i<4;i++){
            o4[i].x += __shfl_xor_sync(0xffffffffu, o4[i].x, o);
            o4[i].y += __shfl_xor_sync(0xffffffffu, o4[i].y, o);
            o4[i].z += __shfl_xor_sync(0xffffffffu, o4[i].z, o);
            o4[i].w += __shfl_xor_sync(0xffffffffu, o4[i].w, o);
        }
    }
    if (rowg == 0){
        #pragma unroll
        for (int i=0;i<4;i++){
            atomicAdd(&scs[i*16+coff+0], o4[i].x);
            atomicAdd(&scs[i*16+coff+1], o4[i].y);
            atomicAdd(&scs[i*16+coff+2], o4[i].z);
            atomicAdd(&scs[i*16+coff+3], o4[i].w);
        }
    }
    __syncthreads();
    if (threadIdx.x < MM)
        g_out_part[(chunk*BB + b)*MM + threadIdx.x] = scs[threadIdx.x];
}

// ---------------- k5: final head ----------------
__global__ void k_final(const float* __restrict__ Wsp, const float* __restrict__ bsp,
                        const float* __restrict__ Wo,  const float* __restrict__ bo,
                        float* __restrict__ out)
{
    const int b=blockIdx.x, t=threadIdx.x;   // 128
    __shared__ float om[MM], seq[HID];
    if (t<MM){
        float s = 0.f;
        #pragma unroll 8
        for (int c=0;c<NCHUNK;c++) s += g_out_part[(c*BB + b)*MM + t];
        om[t] = s + g_aux[b*4+2]*g_ae[b*MM+t];
    }
    __syncthreads();
    for (int j=t; j<HID; j+=128){
        float a = bsp[j];
        #pragma unroll 8
        for (int i=0;i<MM;i++) a = fmaf(om[i], Wsp[i*HID+j], a);
        seq[j] = lrelu(a);
    }
    __syncthreads();
    if (t<SEQW){
        float a = bo[t];
        for (int i=0;i<HID;i++) a = fmaf(seq[i], Wo[i*SEQW+t], a);
        out[b*SEQW+t] = 1.f/(1.f+__expf(-a));
    }
}

// ---------------- launch ----------------
extern "C" void kernel_launch(void* const* d_in, const int* in_sizes, int n_in,
                              void* d_out, int out_size)
{
    const float* x    = (const float*)d_in[0];
    const float* bank = (const float*)d_in[1];
    const float* wrp  = (const float*)d_in[2];
    const float* wwp  = (const float*)d_in[3];
    const float* W0   = (const float*)d_in[4];
    const float* b0   = (const float*)d_in[5];
    const float* W1   = (const float*)d_in[6];
    const float* b1   = (const float*)d_in[7];
    const float* Wc   = (const float*)d_in[8];
    const float* bc   = (const float*)d_in[9];
    const float* Wr   = (const float*)d_in[10];
    const float* br   = (const float*)d_in[11];
    const float* Ww   = (const float*)d_in[12];
    const float* bw   = (const float*)d_in[13];
    const float* Wea  = (const float*)d_in[14];
    const float* bea  = (const float*)d_in[15];
    const float* Wsp  = (const float*)d_in[16];
    const float* bsp  = (const float*)d_in[17];
    const float* Wo   = (const float*)d_in[18];
    const float* bo   = (const float*)d_in[19];
    float* out = (float*)d_out;

    k_ctrlA<<<BB + NCHUNK*BB, 256>>>(bank, x, W0,b0, W1,b1, Wc,bc, Wr,br, Ww,bw, wrp, wwp);
    k_fusedB<<<BB + NCHUNK*BB, 256>>>(bank, Wea, bea);     // ea + passB(dkw,dkr,dae)
    k_addrWR<<<BB, 1024>>>(wwp, wrp);                      // write+read addressing fused
    k_passC<<<dim3(NCHUNK, BB), 256>>>(bank);
    k_final<<<BB, 128>>>(Wsp, bsp, Wo, bo, out);
}

// round 10
// speedup vs baseline: 1.2479x; 1.1742x over previous
#include <cuda_runtime.h>
#include <math.h>

#define BB   128
#define NN   8192
#define MM   64
#define HID  512
#define OUTC 256
#define REPR 70
#define SEQW 63
#define NCHUNK 32           // 256 rows per chunk

// ---------------- scratch (device globals) ----------------
__device__ float g_kr[BB*MM];
__device__ float g_kw[BB*MM];
__device__ float g_par[BB*16];
__device__ float g_ae[BB*MM];
__device__ float g_aux[BB*4];               // 0:||ae||^2  1:ae.kr
__device__ float g_msum_part[NCHUNK*BB*MM];
__device__ float g_dkw[BB*NN];
__device__ float g_dkr[BB*NN];
__device__ float g_n2 [BB*NN];
__device__ float g_dae[BB*NN];
__device__ unsigned g_eadone[BB];           // zero-init; reset each replay by k_mega

__device__ __forceinline__ float lrelu(float v){ return (v>0.f)? v : 0.01f*v; }

// ---- block reductions ----
__device__ __forceinline__ float bredsum(float v, float* sred, int nw){
    const int lane = threadIdx.x & 31, wid = threadIdx.x >> 5;
    #pragma unroll
    for (int o=16;o>0;o>>=1) v += __shfl_xor_sync(0xffffffffu, v, o);
    if (lane==0) sred[wid]=v;
    __syncthreads();
    if (wid==0){
        float w = (lane<nw)? sred[lane] : 0.f;
        #pragma unroll
        for (int o=16;o>0;o>>=1) w += __shfl_xor_sync(0xffffffffu, w, o);
        if (lane==0) sred[0]=w;
    }
    __syncthreads();
    float r = sred[0];
    __syncthreads();
    return r;
}
__device__ __forceinline__ float bredmax(float v, float* sred, int nw){
    const int lane = threadIdx.x & 31, wid = threadIdx.x >> 5;
    #pragma unroll
    for (int o=16;o>0;o>>=1) v = fmaxf(v, __shfl_xor_sync(0xffffffffu, v, o));
    if (lane==0) sred[wid]=v;
    __syncthreads();
    if (wid==0){
        float w = (lane<nw)? sred[lane] : -1e30f;
        #pragma unroll
        for (int o=16;o>0;o>>=1) w = fmaxf(w, __shfl_xor_sync(0xffffffffu, w, o));
        if (lane==0) sred[0]=w;
    }
    __syncthreads();
    float r = sred[0];
    __syncthreads();
    return r;
}

// ---------------- controller body (256 threads) ----------------
__device__ void ctrl_body(int b,
    const float* __restrict__ x,
    const float* __restrict__ W0, const float* __restrict__ b0,
    const float* __restrict__ W1, const float* __restrict__ b1,
    const float* __restrict__ Wc, const float* __restrict__ bc,
    const float* __restrict__ Wr, const float* __restrict__ br,
    const float* __restrict__ Ww, const float* __restrict__ bw,
    const float* __restrict__ wrp, const float* __restrict__ wwp)
{
    const int t = threadIdx.x;
    __shared__ float xs[SEQW+1];
    __shared__ float h0s[HID];
    __shared__ float h1s[HID];
    __shared__ float cs_[OUTC];
    __shared__ float rr[REPR];
    __shared__ float rw[REPR];
    __shared__ float sred[32];

    if (t < SEQW+1) xs[t] = x[b*(SEQW+1)+t];
    __syncthreads();
    {
        float a0 = b0[t], a1 = b0[t+256];
        #pragma unroll
        for (int i=0;i<SEQW+1;i++){
            float v = xs[i];
            a0 = fmaf(v, W0[i*HID + t],     a0);
            a1 = fmaf(v, W0[i*HID + t+256], a1);
        }
        h0s[t] = lrelu(a0); h0s[t+256] = lrelu(a1);
    }
    __syncthreads();
    {
        float a0 = b1[t], a1 = b1[t+256];
        #pragma unroll 8
        for (int i=0;i<HID;i++){
            float v = h0s[i];
            a0 = fmaf(v, W1[i*HID + t],     a0);
            a1 = fmaf(v, W1[i*HID + t+256], a1);
        }
        h1s[t] = lrelu(a0); h1s[t+256] = lrelu(a1);
    }
    __syncthreads();
    {
        float a0 = bc[t];
        #pragma unroll 8
        for (int i=0;i<HID;i++)
            a0 = fmaf(h1s[i], Wc[i*OUTC + t], a0);
        cs_[t] = lrelu(a0);
    }
    __syncthreads();
    if (t < REPR){
        float a = br[t];
        #pragma unroll 8
        for (int i=0;i<OUTC;i++) a = fmaf(cs_[i], Wr[i*REPR + t], a);
        rr[t] = a;
    } else if (t >= 128 && t < 128+REPR){
        const int j = t-128;
        float a = bw[j];
        #pragma unroll 8
        for (int i=0;i<OUTC;i++) a = fmaf(cs_[i], Ww[i*REPR + j], a);
        rw[j] = a;
    }
    __syncthreads();

    float vr = 0.f, vw = 0.f;
    if (t < MM){
        vr = rr[t]; vw = rw[t];
        g_kr[b*MM+t] = vr; g_kw[b*MM+t] = vw;
    }
    float nr = bredsum(vr*vr, sred, 8);
    float nw_ = bredsum(vw*vw, sred, 8);
    if (t==0){ g_par[b*16+12]=sqrtf(nr); g_par[b*16+13]=sqrtf(nw_); }

    const size_t base = (size_t)b*NN;
    float sr=0.f, sw=0.f;
    for (int n=t; n<NN; n+=256){ sr += wrp[base+n]; sw += wwp[base+n]; }
    sr = bredsum(sr, sred, 8);
    sw = bredsum(sw, sred, 8);
    if (t==0){ g_par[b*16+14]=1.f/sr; g_par[b*16+15]=1.f/sw; }

    if (t==0){
        float* p = &g_par[b*16];
        p[0] = fmaxf(rr[64],0.f)+1e-8f;
        p[1] = 1.f/(1.f+__expf(-rr[65]));
        {
            float m = fmaxf(rr[66], fmaxf(rr[67], rr[68]));
            float e0=__expf(rr[66]-m), e1=__expf(rr[67]-m), e2=__expf(rr[68]-m);
            float s=e0+e1+e2;
            p[2]=e0/s; p[3]=e1/s; p[4]=e2/s;
        }
        p[5] = fmaxf(rr[69],0.f)+1.f;
        p[6] = fmaxf(rw[64],0.f)+1e-8f;
        p[7] = 1.f/(1.f+__expf(-rw[65]));
        {
            float m = fmaxf(rw[66], fmaxf(rw[67], rw[68]));
            float e0=__expf(rw[66]-m), e1=__expf(rw[67]-m), e2=__expf(rw[68]-m);
            float s=e0+e1+e2;
            p[8]=e0/s; p[9]=e1/s; p[10]=e2/s;
        }
        p[11] = fmaxf(rw[69],0.f)+1.f;
    }
}

// ---------------- k1: ctrl (blocks 0..127) + passA-lite (n2 + colsums) ----------------
__global__ void __launch_bounds__(256) k_ctrlA(const float* __restrict__ bank,
    const float* __restrict__ x,
    const float* __restrict__ W0, const float* __restrict__ b0,
    const float* __restrict__ W1, const float* __restrict__ b1,
    const float* __restrict__ Wc, const float* __restrict__ bc,
    const float* __restrict__ Wr, const float* __restrict__ br,
    const float* __restrict__ Ww, const float* __restrict__ bw,
    const float* __restrict__ wrp, const float* __restrict__ wwp)
{
    if (blockIdx.x < BB){
        ctrl_body(blockIdx.x, x, W0,b0, W1,b1, Wc,bc, Wr,br, Ww,bw, wrp, wwp);
        return;
    }
    const int u = blockIdx.x - BB;
    const int b = u >> 5, chunk = u & 31;
    const int warp = threadIdx.x >> 5;
    const int lane = threadIdx.x & 31;
    const int sub4 = lane & 3;
    const int rowg = lane >> 2;
    const size_t bbase = (size_t)b * NN;
    const int coff = sub4*4;

    __shared__ float scs[MM];
    if (threadIdx.x < MM) scs[threadIdx.x] = 0.f;

    float4 cs[4];
    #pragma unroll
    for (int i=0;i<4;i++) cs[i] = make_float4(0.f,0.f,0.f,0.f);
    __syncthreads();

    #pragma unroll
    for (int it=0; it<4; it++){
        const int row = chunk*256 + it*64 + warp*8 + rowg;
        const float* rp = bank + (bbase + row)*MM + coff;
        float4 v[4];
        #pragma unroll
        for (int i=0;i<4;i++) v[i] = *reinterpret_cast<const float4*>(rp + i*16);
        float nn = 0.f;
        #pragma unroll
        for (int i=0;i<4;i++){
            nn  = fmaf(v[i].x,v[i].x,nn); nn = fmaf(v[i].y,v[i].y,nn);
            nn  = fmaf(v[i].z,v[i].z,nn); nn = fmaf(v[i].w,v[i].w,nn);
            cs[i].x += v[i].x; cs[i].y += v[i].y; cs[i].z += v[i].z; cs[i].w += v[i].w;
        }
        nn += __shfl_xor_sync(0xffffffffu, nn, 1);
        nn += __shfl_xor_sync(0xffffffffu, nn, 2);
        if (sub4 == 0) g_n2[bbase+row] = nn;
    }
    #pragma unroll
    for (int o=4;o<=16;o<<=1){
        #pragma unroll
        for (int i=0;i<4;i++){
            cs[i].x += __shfl_xor_sync(0xffffffffu, cs[i].x, o);
            cs[i].y += __shfl_xor_sync(0xffffffffu, cs[i].y, o);
            cs[i].z += __shfl_xor_sync(0xffffffffu, cs[i].z, o);
            cs[i].w += __shfl_xor_sync(0xffffffffu, cs[i].w, o);
        }
    }
    if (rowg == 0){
        #pragma unroll
        for (int i=0;i<4;i++){
            atomicAdd(&scs[i*16+coff+0], cs[i].x);
            atomicAdd(&scs[i*16+coff+1], cs[i].y);
            atomicAdd(&scs[i*16+coff+2], cs[i].z);
            atomicAdd(&scs[i*16+coff+3], cs[i].w);
        }
    }
    __syncthreads();
    if (threadIdx.x < MM)
        g_msum_part[(chunk*BB + b)*MM + threadIdx.x] = scs[threadIdx.x];
}

// ---------------- ea body (256 threads) ----------------
__device__ void ea_body(int b, const float* __restrict__ Wea, const float* __restrict__ bea)
{
    __shared__ float ma[MM], kws[MM], eas[2*MM], sred[32];
    const int t = threadIdx.x;
    if (t<MM){
        float s = 0.f;
        #pragma unroll 8
        for (int c=0;c<NCHUNK;c++) s += g_msum_part[(c*BB + b)*MM + t];
        ma[t]  = s * (1.f/(float)NN);
        kws[t] = g_kw[b*MM+t];
    }
    __syncthreads();
    if (t < 2*MM){
        float acc = bea[t];
        #pragma unroll 8
        for (int i=0;i<MM;i++)  acc = fmaf(ma[i],  Wea[i*(2*MM)+t],      acc);
        #pragma unroll 8
        for (int i=0;i<MM;i++)  acc = fmaf(kws[i], Wea[(MM+i)*(2*MM)+t], acc);
        eas[t]=acc;
    }
    __syncthreads();
    float ae=0.f, krv=0.f;
    if (t<MM){
        float e = 1.f/(1.f+__expf(-eas[t]));
        ae = eas[MM+t]-e;
        g_ae[b*MM+t]=ae;
        krv = g_kr[b*MM+t];
    }
    float a2 = bredsum(ae*ae, sred, 8);
    float ak = bredsum(ae*krv, sred, 8);
    if (t==0){
        g_aux[b*4+0]=a2; g_aux[b*4+1]=ak;
        __threadfence();
        atomicExch(&g_eadone[b], 1u);
    }
}

// ---------------- k2: ea (blocks 0..127) + passB (dkw, dkr, dae; 8-lanes-per-row) ----------------
__global__ void __launch_bounds__(256) k_fusedB(const float* __restrict__ bank,
                                                const float* __restrict__ Wea,
                                                const float* __restrict__ bea)
{
    if (blockIdx.x < BB){ ea_body(blockIdx.x, Wea, bea); return; }

    const int u = blockIdx.x - BB;
    const int b = u >> 5, chunk = u & 31;
    const int warp = threadIdx.x >> 5;
    const int lane = threadIdx.x & 31;
    const int sub8 = lane & 7;
    const int rowg = lane >> 3;          // 4 rows per warp-iter
    const size_t bbase = (size_t)b * NN;
    const int coff = sub8*8;             // 8 floats per lane

    if (threadIdx.x == 0){
        while (atomicAdd(&g_eadone[b], 0u) == 0u) __nanosleep(200);
    }
    __syncthreads();
    __threadfence();

    const float4 aeA = *reinterpret_cast<const float4*>(&g_ae[b*MM + coff]);
    const float4 aeB = *reinterpret_cast<const float4*>(&g_ae[b*MM + coff + 4]);
    const float4 krA = *reinterpret_cast<const float4*>(&g_kr[b*MM + coff]);
    const float4 krB = *reinterpret_cast<const float4*>(&g_kr[b*MM + coff + 4]);
    const float4 kwA = *reinterpret_cast<const float4*>(&g_kw[b*MM + coff]);
    const float4 kwB = *reinterpret_cast<const float4*>(&g_kw[b*MM + coff + 4]);

    #pragma unroll
    for (int it=0; it<8; it++){
        const int row = chunk*256 + it*32 + warp*4 + rowg;
        const float* rp = bank + (bbase + row)*MM + coff;
        const float4 v0 = *reinterpret_cast<const float4*>(rp);
        const float4 v1 = *reinterpret_cast<const float4*>(rp + 4);
        float dw=0.f, dk=0.f, da=0.f;
        dw=fmaf(v0.x,kwA.x,dw); dw=fmaf(v0.y,kwA.y,dw); dw=fmaf(v0.z,kwA.z,dw); dw=fmaf(v0.w,kwA.w,dw);
        dw=fmaf(v1.x,kwB.x,dw); dw=fmaf(v1.y,kwB.y,dw); dw=fmaf(v1.z,kwB.z,dw); dw=fmaf(v1.w,kwB.w,dw);
        dk=fmaf(v0.x,krA.x,dk); dk=fmaf(v0.y,krA.y,dk); dk=fmaf(v0.z,krA.z,dk); dk=fmaf(v0.w,krA.w,dk);
        dk=fmaf(v1.x,krB.x,dk); dk=fmaf(v1.y,krB.y,dk); dk=fmaf(v1.z,krB.z,dk); dk=fmaf(v1.w,krB.w,dk);
        da=fmaf(v0.x,aeA.x,da); da=fmaf(v0.y,aeA.y,da); da=fmaf(v0.z,aeA.z,da); da=fmaf(v0.w,aeA.w,da);
        da=fmaf(v1.x,aeB.x,da); da=fmaf(v1.y,aeB.y,da); da=fmaf(v1.z,aeB.z,da); da=fmaf(v1.w,aeB.w,da);
        #pragma unroll
        for (int o=1;o<8;o<<=1){
            dw += __shfl_xor_sync(0xffffffffu, dw, o);
            dk += __shfl_xor_sync(0xffffffffu, dk, o);
            da += __shfl_xor_sync(0xffffffffu, da, o);
        }
        if (sub8 == 0){
            g_dkw[bbase+row] = dw;
            g_dkr[bbase+row] = dk;
            g_dae[bbase+row] = da;
        }
    }
}

// ---------------- k3: MEGA — addrW + addrR + weighted read + final head (1 block/batch) ----------------
__global__ void __launch_bounds__(1024) k_mega(const float* __restrict__ bank,
                                               const float* __restrict__ wwp,
                                               const float* __restrict__ wrp,
                                               const float* __restrict__ Wsp,
                                               const float* __restrict__ bsp,
                                               const float* __restrict__ Wo,
                                               const float* __restrict__ bo,
                                               float* __restrict__ out)
{
    __shared__ float arr[NN];       // wg scratch, then wr
    __shared__ float sred[32];
    __shared__ float scs[MM];
    __shared__ float om[MM];
    __shared__ float seq[HID];
    const int b = blockIdx.x;
    const int t = threadIdx.x;
    if (t==0) g_eadone[b] = 0u;     // reset for next graph replay
    if (t<MM) scs[t] = 0.f;
    const size_t base = (size_t)b*NN;
    const float* p = &g_par[b*16];

    float ww_loc[8];
    float S;

    // ======= WRITE addressing =======
    {
        const float beta=p[6], gg=p[7], s0=p[8], s1=p[9], s2=p[10], gamma=p[11];
        const float nk=p[13], invs=p[15];
        float lmax = -1e30f;
        #pragma unroll
        for (int i=0;i<8;i++){
            int n = t + i*1024;
            float cosv = __fdividef(g_dkw[base+n], fmaxf(sqrtf(g_n2[base+n])*nk, 1e-8f));
            float tv = beta*cosv;
            arr[n]=tv;
            lmax = fmaxf(lmax, tv);
        }
        const float bmax = bredmax(lmax, sred, 32);
        float lsum=0.f;
        #pragma unroll
        for (int i=0;i<8;i++){
            int n=t+i*1024;
            float e = __expf(arr[n]-bmax);
            arr[n]=e; lsum+=e;
        }
        const float invsum = __fdividef(1.f, bredsum(lsum, sred, 32));
        #pragma unroll
        for (int i=0;i<8;i++){
            int n=t+i*1024;
            float wc  = arr[n]*invsum;
            arr[n] = gg*wc + (1.f-gg)*wwp[base+n]*invs;
        }
        __syncthreads();
        float lps=0.f;
        #pragma unroll
        for (int i=0;i<8;i++){
            int n=t+i*1024;
            float ws = s0*arr[(n+NN-1)&(NN-1)] + s1*arr[n] + s2*arr[(n+1)&(NN-1)];
            float wp = __powf(ws, gamma);
            ww_loc[i]=wp; lps+=wp;
        }
        const float invp = __fdividef(1.f, bredsum(lps, sred, 32));
        #pragma unroll
        for (int i=0;i<8;i++) ww_loc[i] *= invp;
    }
    __syncthreads();   // arr reuse barrier

    // ======= READ addressing (virtual new_bank via rank-1 algebra) =======
    {
        const float beta=p[0], gg=p[1], s0=p[2], s1=p[3], s2=p[4], gamma=p[5];
        const float nk=p[12], invs=p[14];
        const float ae2=g_aux[b*4], aekr=g_aux[b*4+1];
        float lmax = -1e30f;
        #pragma unroll
        for (int i=0;i<8;i++){
            int n = t + i*1024;
            float w  = ww_loc[i];
            float d  = g_dkr[base+n] + w*aekr;
            float nn = fmaxf(g_n2[base+n] + 2.f*w*g_dae[base+n] + w*w*ae2, 0.f);
            float cosv = __fdividef(d, fmaxf(sqrtf(nn)*nk, 1e-8f));
            float tv = beta*cosv;
            arr[n]=tv;
            lmax = fmaxf(lmax, tv);
        }
        const float bmax = bredmax(lmax, sred, 32);
        float lsum=0.f;
        #pragma unroll
        for (int i=0;i<8;i++){
            int n=t+i*1024;
            float e = __expf(arr[n]-bmax);
            arr[n]=e; lsum+=e;
        }
        const float invsum = __fdividef(1.f, bredsum(lsum, sred, 32));
        #pragma unroll
        for (int i=0;i<8;i++){
            int n=t+i*1024;
            float wc  = arr[n]*invsum;
            arr[n] = gg*wc + (1.f-gg)*wrp[base+n]*invs;
        }
        __syncthreads();
        float wp_loc[8];
        float lps=0.f;
        #pragma unroll
        for (int i=0;i<8;i++){
            int n=t+i*1024;
            float ws = s0*arr[(n+NN-1)&(NN-1)] + s1*arr[n] + s2*arr[(n+1)&(NN-1)];
            float wp = __powf(ws, gamma);
            wp_loc[i]=wp; lps+=wp;
        }
        const float invp = __fdividef(1.f, bredsum(lps, sred, 32));   // has syncthreads: shift reads done
        float lS=0.f;
        #pragma unroll
        for (int i=0;i<8;i++){
            int n=t+i*1024;
            float w = wp_loc[i]*invp;
            arr[n] = w;                 // arr now holds w_r
            lS += ww_loc[i]*w;
        }
        S = bredsum(lS, sred, 32);      // includes syncthreads -> arr writes visible
    }

    // ======= Weighted read: out_raw[m] = sum_n bank[b,n,m] * wr[n] =======
    {
        const int lane = t & 31;
        const int warp = t >> 5;         // 32 warps
        const int sub16 = lane & 15;
        const int half = lane >> 4;
        float4 acc = make_float4(0.f,0.f,0.f,0.f);
        const float* bp = bank + base*MM + sub16*4;

        #pragma unroll 1
        for (int it=0; it<32; it++){
            float4 v[4]; float w4[4]; int row[4];
            #pragma unroll
            for (int j=0;j<4;j++){
                row[j] = (it*4+j)*64 + warp*2 + half;
                v[j] = *reinterpret_cast<const float4*>(bp + (size_t)row[j]*MM);
                w4[j] = arr[row[j]];
            }
            #pragma unroll
            for (int j=0;j<4;j++){
                acc.x = fmaf(v[j].x, w4[j], acc.x);
                acc.y = fmaf(v[j].y, w4[j], acc.y);
                acc.z = fmaf(v[j].z, w4[j], acc.z);
                acc.w = fmaf(v[j].w, w4[j], acc.w);
            }
        }
        acc.x += __shfl_xor_sync(0xffffffffu, acc.x, 16);
        acc.y += __shfl_xor_sync(0xffffffffu, acc.y, 16);
        acc.z += __shfl_xor_sync(0xffffffffu, acc.z, 16);
        acc.w += __shfl_xor_sync(0xffffffffu, acc.w, 16);
        if (half == 0){
            atomicAdd(&scs[sub16*4+0], acc.x);
            atomicAdd(&scs[sub16*4+1], acc.y);
            atomicAdd(&scs[sub16*4+2], acc.z);
            atomicAdd(&scs[sub16*4+3], acc.w);
        }
        __syncthreads();
    }

    // ======= final head =======
    if (t<MM) om[t] = scs[t] + S*g_ae[b*MM+t];
    __syncthreads();
    if (t<HID){
        float a = bsp[t];
        #pragma unroll 8
        for (int i=0;i<MM;i++) a = fmaf(om[i], Wsp[i*HID+t], a);
        seq[t] = lrelu(a);
    }
    __syncthreads();
    if (t<SEQW){
        float a = bo[t];
        for (int i=0;i<HID;i++) a = fmaf(seq[i], Wo[i*SEQW+t], a);
        out[b*SEQW+t] = 1.f/(1.f+__expf(-a));
    }
}

// ---------------- launch ----------------
extern "C" void kernel_launch(void* const* d_in, const int* in_sizes, int n_in,
                              void* d_out, int out_size)
{
    const float* x    = (const float*)d_in[0];
    const float* bank = (const float*)d_in[1];
    const float* wrp  = (const float*)d_in[2];
    const float* wwp  = (const float*)d_in[3];
    const float* W0   = (const float*)d_in[4];
    const float* b0   = (const float*)d_in[5];
    const float* W1   = (const float*)d_in[6];
    const float* b1   = (const float*)d_in[7];
    const float* Wc   = (const float*)d_in[8];
    const float* bc   = (const float*)d_in[9];
    const float* Wr   = (const float*)d_in[10];
    const float* br   = (const float*)d_in[11];
    const float* Ww   = (const float*)d_in[12];
    const float* bw   = (const float*)d_in[13];
    const float* Wea  = (const float*)d_in[14];
    const float* bea  = (const float*)d_in[15];
    const float* Wsp  = (const float*)d_in[16];
    const float* bsp  = (const float*)d_in[17];
    const float* Wo   = (const float*)d_in[18];
    const float* bo   = (const float*)d_in[19];
    float* out = (float*)d_out;

    k_ctrlA<<<BB + NCHUNK*BB, 256>>>(bank, x, W0,b0, W1,b1, Wc,bc, Wr,br, Ww,bw, wrp, wwp);
    k_fusedB<<<BB + NCHUNK*BB, 256>>>(bank, Wea, bea);     // ea + passB(dkw,dkr,dae)
    k_mega<<<BB, 1024>>>(bank, wwp, wrp, Wsp, bsp, Wo, bo, out);  // addrW+addrR+read+head
}

// round 11
// speedup vs baseline: 1.2903x; 1.0339x over previous
#include <cuda_runtime.h>
#include <math.h>

#define BB   128
#define NN   8192
#define MM   64
#define HID  512
#define OUTC 256
#define REPR 70
#define SEQW 63
#define NCHUNK 32           // 256 rows per chunk

// ---------------- scratch (device globals) ----------------
__device__ float g_kr[BB*MM];
__device__ float g_kw[BB*MM];
__device__ float g_par[BB*16];
__device__ float g_ae[BB*MM];
__device__ float g_aux[BB*4];               // 0:||ae||^2  1:ae.kr
__device__ float g_msum_part[NCHUNK*BB*MM];
__device__ float g_dkw[BB*NN];
__device__ float g_dkr[BB*NN];
__device__ float g_n2 [BB*NN];
__device__ float g_dae[BB*NN];
__device__ unsigned g_ctrldone[BB];         // zero-init; reset each replay by k_mega
__device__ unsigned g_eadone[BB];

__device__ __forceinline__ float lrelu(float v){ return (v>0.f)? v : 0.01f*v; }

// ---- block reductions ----
__device__ __forceinline__ float bredsum(float v, float* sred, int nw){
    const int lane = threadIdx.x & 31, wid = threadIdx.x >> 5;
    #pragma unroll
    for (int o=16;o>0;o>>=1) v += __shfl_xor_sync(0xffffffffu, v, o);
    if (lane==0) sred[wid]=v;
    __syncthreads();
    if (wid==0){
        float w = (lane<nw)? sred[lane] : 0.f;
        #pragma unroll
        for (int o=16;o>0;o>>=1) w += __shfl_xor_sync(0xffffffffu, w, o);
        if (lane==0) sred[0]=w;
    }
    __syncthreads();
    float r = sred[0];
    __syncthreads();
    return r;
}
__device__ __forceinline__ float bredmax(float v, float* sred, int nw){
    const int lane = threadIdx.x & 31, wid = threadIdx.x >> 5;
    #pragma unroll
    for (int o=16;o>0;o>>=1) v = fmaxf(v, __shfl_xor_sync(0xffffffffu, v, o));
    if (lane==0) sred[wid]=v;
    __syncthreads();
    if (wid==0){
        float w = (lane<nw)? sred[lane] : -1e30f;
        #pragma unroll
        for (int o=16;o>0;o>>=1) w = fmaxf(w, __shfl_xor_sync(0xffffffffu, w, o));
        if (lane==0) sred[0]=w;
    }
    __syncthreads();
    float r = sred[0];
    __syncthreads();
    return r;
}

// ---------------- k1: pass A (pure streaming): n2 + column sums ----------------
__global__ void __launch_bounds__(256) k_passA(const float* __restrict__ bank)
{
    const int u = blockIdx.x;
    const int b = u >> 5, chunk = u & 31;
    const int warp = threadIdx.x >> 5;
    const int lane = threadIdx.x & 31;
    const int sub4 = lane & 3;
    const int rowg = lane >> 2;
    const size_t bbase = (size_t)b * NN;
    const int coff = sub4*4;

    __shared__ float scs[MM];
    if (threadIdx.x < MM) scs[threadIdx.x] = 0.f;

    float4 cs[4];
    #pragma unroll
    for (int i=0;i<4;i++) cs[i] = make_float4(0.f,0.f,0.f,0.f);
    __syncthreads();

    #pragma unroll
    for (int it=0; it<4; it++){
        const int row = chunk*256 + it*64 + warp*8 + rowg;
        const float* rp = bank + (bbase + row)*MM + coff;
        float4 v[4];
        #pragma unroll
        for (int i=0;i<4;i++) v[i] = *reinterpret_cast<const float4*>(rp + i*16);
        float nn = 0.f;
        #pragma unroll
        for (int i=0;i<4;i++){
            nn  = fmaf(v[i].x,v[i].x,nn); nn = fmaf(v[i].y,v[i].y,nn);
            nn  = fmaf(v[i].z,v[i].z,nn); nn = fmaf(v[i].w,v[i].w,nn);
            cs[i].x += v[i].x; cs[i].y += v[i].y; cs[i].z += v[i].z; cs[i].w += v[i].w;
        }
        nn += __shfl_xor_sync(0xffffffffu, nn, 1);
        nn += __shfl_xor_sync(0xffffffffu, nn, 2);
        if (sub4 == 0) g_n2[bbase+row] = nn;
    }
    #pragma unroll
    for (int o=4;o<=16;o<<=1){
        #pragma unroll
        for (int i=0;i<4;i++){
            cs[i].x += __shfl_xor_sync(0xffffffffu, cs[i].x, o);
            cs[i].y += __shfl_xor_sync(0xffffffffu, cs[i].y, o);
            cs[i].z += __shfl_xor_sync(0xffffffffu, cs[i].z, o);
            cs[i].w += __shfl_xor_sync(0xffffffffu, cs[i].w, o);
        }
    }
    if (rowg == 0){
        #pragma unroll
        for (int i=0;i<4;i++){
            atomicAdd(&scs[i*16+coff+0], cs[i].x);
            atomicAdd(&scs[i*16+coff+1], cs[i].y);
            atomicAdd(&scs[i*16+coff+2], cs[i].z);
            atomicAdd(&scs[i*16+coff+3], cs[i].w);
        }
    }
    __syncthreads();
    if (threadIdx.x < MM)
        g_msum_part[(chunk*BB + b)*MM + threadIdx.x] = scs[threadIdx.x];
}

// ---------------- controller body (256 threads) ----------------
__device__ void ctrl_body(int b,
    const float* __restrict__ x,
    const float* __restrict__ W0, const float* __restrict__ b0,
    const float* __restrict__ W1, const float* __restrict__ b1,
    const float* __restrict__ Wc, const float* __restrict__ bc,
    const float* __restrict__ Wr, const float* __restrict__ br,
    const float* __restrict__ Ww, const float* __restrict__ bw,
    const float* __restrict__ wrp, const float* __restrict__ wwp)
{
    const int t = threadIdx.x;
    __shared__ float xs[SEQW+1];
    __shared__ float h0s[HID];
    __shared__ float h1s[HID];
    __shared__ float cs_[OUTC];
    __shared__ float rr[REPR];
    __shared__ float rw[REPR];
    __shared__ float sred[32];

    if (t < SEQW+1) xs[t] = x[b*(SEQW+1)+t];
    __syncthreads();
    {
        float a0 = b0[t], a1 = b0[t+256];
        #pragma unroll
        for (int i=0;i<SEQW+1;i++){
            float v = xs[i];
            a0 = fmaf(v, W0[i*HID + t],     a0);
            a1 = fmaf(v, W0[i*HID + t+256], a1);
        }
        h0s[t] = lrelu(a0); h0s[t+256] = lrelu(a1);
    }
    __syncthreads();
    {
        float a0 = b1[t], a1 = b1[t+256];
        #pragma unroll 16
        for (int i=0;i<HID;i++){
            float v = h0s[i];
            a0 = fmaf(v, W1[i*HID + t],     a0);
            a1 = fmaf(v, W1[i*HID + t+256], a1);
        }
        h1s[t] = lrelu(a0); h1s[t+256] = lrelu(a1);
    }
    __syncthreads();
    {
        float a0 = bc[t];
        #pragma unroll 16
        for (int i=0;i<HID;i++)
            a0 = fmaf(h1s[i], Wc[i*OUTC + t], a0);
        cs_[t] = lrelu(a0);
    }
    __syncthreads();
    if (t < REPR){
        float a = br[t];
        #pragma unroll 16
        for (int i=0;i<OUTC;i++) a = fmaf(cs_[i], Wr[i*REPR + t], a);
        rr[t] = a;
    } else if (t >= 128 && t < 128+REPR){
        const int j = t-128;
        float a = bw[j];
        #pragma unroll 16
        for (int i=0;i<OUTC;i++) a = fmaf(cs_[i], Ww[i*REPR + j], a);
        rw[j] = a;
    }
    __syncthreads();

    float vr = 0.f, vw = 0.f;
    if (t < MM){
        vr = rr[t]; vw = rw[t];
        g_kr[b*MM+t] = vr; g_kw[b*MM+t] = vw;
    }
    float nr = bredsum(vr*vr, sred, 8);
    float nw_ = bredsum(vw*vw, sred, 8);
    if (t==0){ g_par[b*16+12]=sqrtf(nr); g_par[b*16+13]=sqrtf(nw_); }

    const size_t base = (size_t)b*NN;
    float sr=0.f, sw=0.f;
    for (int n=t; n<NN; n+=256){ sr += wrp[base+n]; sw += wwp[base+n]; }
    sr = bredsum(sr, sred, 8);
    sw = bredsum(sw, sred, 8);
    if (t==0){ g_par[b*16+14]=1.f/sr; g_par[b*16+15]=1.f/sw; }

    if (t==0){
        float* p = &g_par[b*16];
        p[0] = fmaxf(rr[64],0.f)+1e-8f;
        p[1] = 1.f/(1.f+__expf(-rr[65]));
        {
            float m = fmaxf(rr[66], fmaxf(rr[67], rr[68]));
            float e0=__expf(rr[66]-m), e1=__expf(rr[67]-m), e2=__expf(rr[68]-m);
            float s=e0+e1+e2;
            p[2]=e0/s; p[3]=e1/s; p[4]=e2/s;
        }
        p[5] = fmaxf(rr[69],0.f)+1.f;
        p[6] = fmaxf(rw[64],0.f)+1e-8f;
        p[7] = 1.f/(1.f+__expf(-rw[65]));
        {
            float m = fmaxf(rw[66], fmaxf(rw[67], rw[68]));
            float e0=__expf(rw[66]-m), e1=__expf(rw[67]-m), e2=__expf(rw[68]-m);
            float s=e0+e1+e2;
            p[8]=e0/s; p[9]=e1/s; p[10]=e2/s;
        }
        p[11] = fmaxf(rw[69],0.f)+1.f;
    }
    __threadfence();
    __syncthreads();
    if (t==0) atomicExch(&g_ctrldone[b], 1u);
}

// ---------------- ea body (256 threads) ----------------
__device__ void ea_body(int b, const float* __restrict__ Wea, const float* __restrict__ bea)
{
    __shared__ float ma[MM], kws[MM], eas[2*MM], sred[32];
    const int t = threadIdx.x;
    if (t == 0){
        while (atomicAdd(&g_ctrldone[b], 0u) == 0u) __nanosleep(200);
    }
    __syncthreads();
    __threadfence();

    if (t<MM){
        float s = 0.f;
        #pragma unroll 8
        for (int c=0;c<NCHUNK;c++) s += g_msum_part[(c*BB + b)*MM + t];
        ma[t]  = s * (1.f/(float)NN);
        kws[t] = g_kw[b*MM+t];
    }
    __syncthreads();
    if (t < 2*MM){
        float acc = bea[t];
        #pragma unroll 8
        for (int i=0;i<MM;i++)  acc = fmaf(ma[i],  Wea[i*(2*MM)+t],      acc);
        #pragma unroll 8
        for (int i=0;i<MM;i++)  acc = fmaf(kws[i], Wea[(MM+i)*(2*MM)+t], acc);
        eas[t]=acc;
    }
    __syncthreads();
    float ae=0.f, krv=0.f;
    if (t<MM){
        float e = 1.f/(1.f+__expf(-eas[t]));
        ae = eas[MM+t]-e;
        g_ae[b*MM+t]=ae;
        krv = g_kr[b*MM+t];
    }
    float a2 = bredsum(ae*ae, sred, 8);
    float ak = bredsum(ae*krv, sred, 8);
    if (t==0){
        g_aux[b*4+0]=a2; g_aux[b*4+1]=ak;
        __threadfence();
        atomicExch(&g_eadone[b], 1u);
    }
}

// ---------------- k2: ctrl [0,128) + ea [128,256) + passB (spin on ea) ----------------
__global__ void __launch_bounds__(256) k_ctrlB(const float* __restrict__ bank,
    const float* __restrict__ x,
    const float* __restrict__ W0, const float* __restrict__ b0,
    const float* __restrict__ W1, const float* __restrict__ b1,
    const float* __restrict__ Wc, const float* __restrict__ bc,
    const float* __restrict__ Wr, const float* __restrict__ br,
    const float* __restrict__ Ww, const float* __restrict__ bw,
    const float* __restrict__ Wea, const float* __restrict__ bea,
    const float* __restrict__ wrp, const float* __restrict__ wwp)
{
    if (blockIdx.x < BB){
        ctrl_body(blockIdx.x, x, W0,b0, W1,b1, Wc,bc, Wr,br, Ww,bw, wrp, wwp);
        return;
    }
    if (blockIdx.x < 2*BB){ ea_body(blockIdx.x - BB, Wea, bea); return; }

    const int u = blockIdx.x - 2*BB;
    const int b = u >> 5, chunk = u & 31;
    const int warp = threadIdx.x >> 5;
    const int lane = threadIdx.x & 31;
    const int sub8 = lane & 7;
    const int rowg = lane >> 3;          // 4 rows per warp-iter
    const size_t bbase = (size_t)b * NN;
    const int coff = sub8*8;             // 8 floats per lane

    if (threadIdx.x == 0){
        while (atomicAdd(&g_eadone[b], 0u) == 0u) __nanosleep(200);
    }
    __syncthreads();
    __threadfence();

    const float4 aeA = *reinterpret_cast<const float4*>(&g_ae[b*MM + coff]);
    const float4 aeB = *reinterpret_cast<const float4*>(&g_ae[b*MM + coff + 4]);
    const float4 krA = *reinterpret_cast<const float4*>(&g_kr[b*MM + coff]);
    const float4 krB = *reinterpret_cast<const float4*>(&g_kr[b*MM + coff + 4]);
    const float4 kwA = *reinterpret_cast<const float4*>(&g_kw[b*MM + coff]);
    const float4 kwB = *reinterpret_cast<const float4*>(&g_kw[b*MM + coff + 4]);

    #pragma unroll
    for (int it=0; it<8; it++){
        const int row = chunk*256 + it*32 + warp*4 + rowg;
        const float* rp = bank + (bbase + row)*MM + coff;
        const float4 v0 = *reinterpret_cast<const float4*>(rp);
        const float4 v1 = *reinterpret_cast<const float4*>(rp + 4);
        float dw=0.f, dk=0.f, da=0.f;
        dw=fmaf(v0.x,kwA.x,dw); dw=fmaf(v0.y,kwA.y,dw); dw=fmaf(v0.z,kwA.z,dw); dw=fmaf(v0.w,kwA.w,dw);
        dw=fmaf(v1.x,kwB.x,dw); dw=fmaf(v1.y,kwB.y,dw); dw=fmaf(v1.z,kwB.z,dw); dw=fmaf(v1.w,kwB.w,dw);
        dk=fmaf(v0.x,krA.x,dk); dk=fmaf(v0.y,krA.y,dk); dk=fmaf(v0.z,krA.z,dk); dk=fmaf(v0.w,krA.w,dk);
        dk=fmaf(v1.x,krB.x,dk); dk=fmaf(v1.y,krB.y,dk); dk=fmaf(v1.z,krB.z,dk); dk=fmaf(v1.w,krB.w,dk);
        da=fmaf(v0.x,aeA.x,da); da=fmaf(v0.y,aeA.y,da); da=fmaf(v0.z,aeA.z,da); da=fmaf(v0.w,aeA.w,da);
        da=fmaf(v1.x,aeB.x,da); da=fmaf(v1.y,aeB.y,da); da=fmaf(v1.z,aeB.z,da); da=fmaf(v1.w,aeB.w,da);
        #pragma unroll
        for (int o=1;o<8;o<<=1){
            dw += __shfl_xor_sync(0xffffffffu, dw, o);
            dk += __shfl_xor_sync(0xffffffffu, dk, o);
            da += __shfl_xor_sync(0xffffffffu, da, o);
        }
        if (sub8 == 0){
            g_dkw[bbase+row] = dw;
            g_dkr[bbase+row] = dk;
            g_dae[bbase+row] = da;
        }
    }
}

// ---------------- k3: MEGA — addrW + addrR + weighted read + final head (1 block/batch) ----------------
__global__ void __launch_bounds__(1024) k_mega(const float* __restrict__ bank,
                                               const float* __restrict__ wwp,
                                               const float* __restrict__ wrp,
                                               const float* __restrict__ Wsp,
                                               const float* __restrict__ bsp,
                                               const float* __restrict__ Wo,
                                               const float* __restrict__ bo,
                                               float* __restrict__ out)
{
    __shared__ float arr[NN];       // wg scratch, then wr
    __shared__ float sred[32];
    __shared__ float scs[MM];
    __shared__ float om[MM];
    __shared__ float seq[HID];
    const int b = blockIdx.x;
    const int t = threadIdx.x;
    if (t==0){ g_eadone[b] = 0u; g_ctrldone[b] = 0u; }   // reset for next graph replay
    if (t<MM) scs[t] = 0.f;
    const size_t base = (size_t)b*NN;
    const float* p = &g_par[b*16];

    float ww_loc[8];
    float S;

    // ======= WRITE addressing =======
    {
        const float beta=p[6], gg=p[7], s0=p[8], s1=p[9], s2=p[10], gamma=p[11];
        const float nk=p[13], invs=p[15];
        float lmax = -1e30f;
        #pragma unroll
        for (int i=0;i<8;i++){
            int n = t + i*1024;
            float cosv = __fdividef(g_dkw[base+n], fmaxf(sqrtf(g_n2[base+n])*nk, 1e-8f));
            float tv = beta*cosv;
            arr[n]=tv;
            lmax = fmaxf(lmax, tv);
        }
        const float bmax = bredmax(lmax, sred, 32);
        float lsum=0.f;
        #pragma unroll
        for (int i=0;i<8;i++){
            int n=t+i*1024;
            float e = __expf(arr[n]-bmax);
            arr[n]=e; lsum+=e;
        }
        const float invsum = __fdividef(1.f, bredsum(lsum, sred, 32));
        #pragma unroll
        for (int i=0;i<8;i++){
            int n=t+i*1024;
            float wc  = arr[n]*invsum;
            arr[n] = gg*wc + (1.f-gg)*wwp[base+n]*invs;
        }
        __syncthreads();
        float lps=0.f;
        #pragma unroll
        for (int i=0;i<8;i++){
            int n=t+i*1024;
            float ws = s0*arr[(n+NN-1)&(NN-1)] + s1*arr[n] + s2*arr[(n+1)&(NN-1)];
            float wp = __powf(ws, gamma);
            ww_loc[i]=wp; lps+=wp;
        }
        const float invp = __fdividef(1.f, bredsum(lps, sred, 32));
        #pragma unroll
        for (int i=0;i<8;i++) ww_loc[i] *= invp;
    }
    __syncthreads();   // arr reuse barrier

    // ======= READ addressing (virtual new_bank via rank-1 algebra) =======
    {
        const float beta=p[0], gg=p[1], s0=p[2], s1=p[3], s2=p[4], gamma=p[5];
        const float nk=p[12], invs=p[14];
        const float ae2=g_aux[b*4], aekr=g_aux[b*4+1];
        float lmax = -1e30f;
        #pragma unroll
        for (int i=0;i<8;i++){
            int n = t + i*1024;
            float w  = ww_loc[i];
            float d  = g_dkr[base+n] + w*aekr;
            float nn = fmaxf(g_n2[base+n] + 2.f*w*g_dae[base+n] + w*w*ae2, 0.f);
            float cosv = __fdividef(d, fmaxf(sqrtf(nn)*nk, 1e-8f));
            float tv = beta*cosv;
            arr[n]=tv;
            lmax = fmaxf(lmax, tv);
        }
        const float bmax = bredmax(lmax, sred, 32);
        float lsum=0.f;
        #pragma unroll
        for (int i=0;i<8;i++){
            int n=t+i*1024;
            float e = __expf(arr[n]-bmax);
            arr[n]=e; lsum+=e;
        }
        const float invsum = __fdividef(1.f, bredsum(lsum, sred, 32));
        #pragma unroll
        for (int i=0;i<8;i++){
            int n=t+i*1024;
            float wc  = arr[n]*invsum;
            arr[n] = gg*wc + (1.f-gg)*wrp[base+n]*invs;
        }
        __syncthreads();
        float wp_loc[8];
        float lps=0.f;
        #pragma unroll
        for (int i=0;i<8;i++){
            int n=t+i*1024;
            float ws = s0*arr[(n+NN-1)&(NN-1)] + s1*arr[n] + s2*arr[(n+1)&(NN-1)];
            float wp = __powf(ws, gamma);
            wp_loc[i]=wp; lps+=wp;
        }
        const float invp = __fdividef(1.f, bredsum(lps, sred, 32));   // barrier: shift reads done
        float lS=0.f;
        #pragma unroll
        for (int i=0;i<8;i++){
            int n=t+i*1024;
            float w = wp_loc[i]*invp;
            arr[n] = w;                 // arr now holds w_r
            lS += ww_loc[i]*w;
        }
        S = bredsum(lS, sred, 32);      // barrier: arr writes visible
    }

    // ======= Weighted read: out_raw[m] = sum_n bank[b,n,m] * wr[n] =======
    {
        const int lane = t & 31;
        const int warp = t >> 5;         // 32 warps
        const int sub16 = lane & 15;
        const int half = lane >> 4;
        float4 acc = make_float4(0.f,0.f,0.f,0.f);
        const float* bp = bank + base*MM + sub16*4;

        #pragma unroll 1
        for (int it=0; it<32; it++){
            float4 v[4]; float w4[4]; int row[4];
            #pragma unroll
            for (int j=0;j<4;j++){
                row[j] = (it*4+j)*64 + warp*2 + half;
                v[j] = *reinterpret_cast<const float4*>(bp + (size_t)row[j]*MM);
                w4[j] = arr[row[j]];
            }
            #pragma unroll
            for (int j=0;j<4;j++){
                acc.x = fmaf(v[j].x, w4[j], acc.x);
                acc.y = fmaf(v[j].y, w4[j], acc.y);
                acc.z = fmaf(v[j].z, w4[j], acc.z);
                acc.w = fmaf(v[j].w, w4[j], acc.w);
            }
        }
        acc.x += __shfl_xor_sync(0xffffffffu, acc.x, 16);
        acc.y += __shfl_xor_sync(0xffffffffu, acc.y, 16);
        acc.z += __shfl_xor_sync(0xffffffffu, acc.z, 16);
        acc.w += __shfl_xor_sync(0xffffffffu, acc.w, 16);
        if (half == 0){
            atomicAdd(&scs[sub16*4+0], acc.x);
            atomicAdd(&scs[sub16*4+1], acc.y);
            atomicAdd(&scs[sub16*4+2], acc.z);
            atomicAdd(&scs[sub16*4+3], acc.w);
        }
        __syncthreads();
    }

    // ======= final head =======
    if (t<MM) om[t] = scs[t] + S*g_ae[b*MM+t];
    __syncthreads();
    if (t<HID){
        float a = bsp[t];
        #pragma unroll 8
        for (int i=0;i<MM;i++) a = fmaf(om[i], Wsp[i*HID+t], a);
        seq[t] = lrelu(a);
    }
    __syncthreads();
    if (t<SEQW){
        float a = bo[t];
        for (int i=0;i<HID;i++) a = fmaf(seq[i], Wo[i*SEQW+t], a);
        out[b*SEQW+t] = 1.f/(1.f+__expf(-a));
    }
}

// ---------------- launch ----------------
extern "C" void kernel_launch(void* const* d_in, const int* in_sizes, int n_in,
                              void* d_out, int out_size)
{
    const float* x    = (const float*)d_in[0];
    const float* bank = (const float*)d_in[1];
    const float* wrp  = (const float*)d_in[2];
    const float* wwp  = (const float*)d_in[3];
    const float* W0   = (const float*)d_in[4];
    const float* b0   = (const float*)d_in[5];
    const float* W1   = (const float*)d_in[6];
    const float* b1   = (const float*)d_in[7];
    const float* Wc   = (const float*)d_in[8];
    const float* bc   = (const float*)d_in[9];
    const float* Wr   = (const float*)d_in[10];
    const float* br   = (const float*)d_in[11];
    const float* Ww   = (const float*)d_in[12];
    const float* bw   = (const float*)d_in[13];
    const float* Wea  = (const float*)d_in[14];
    const float* bea  = (const float*)d_in[15];
    const float* Wsp  = (const float*)d_in[16];
    const float* bsp  = (const float*)d_in[17];
    const float* Wo   = (const float*)d_in[18];
    const float* bo   = (const float*)d_in[19];
    float* out = (float*)d_out;

    k_passA<<<NCHUNK*BB, 256>>>(bank);                    // pure streaming: n2 + colsums
    k_ctrlB<<<2*BB + NCHUNK*BB, 256>>>(bank, x, W0,b0, W1,b1, Wc,bc, Wr,br, Ww,bw,
                                       Wea,bea, wrp, wwp); // ctrl + ea + passB
    k_mega<<<BB, 1024>>>(bank, wwp, wrp, Wsp, bsp, Wo, bo, out);
}

// round 12
// speedup vs baseline: 1.3130x; 1.0176x over previous
#include <cuda_runtime.h>
#include <math.h>

#define BB   128
#define NN   8192
#define MM   64
#define HID  512
#define OUTC 256
#define REPR 70
#define SEQW 63
#define NCHUNK 32           // 256 rows per chunk

// ---------------- scratch (device globals) ----------------
__device__ float g_kr[BB*MM];
__device__ float g_kw[BB*MM];
__device__ float g_par[BB*16];
__device__ float g_ae[BB*MM];
__device__ float g_aux[BB*4];               // 0:||ae||^2  1:ae.kr
__device__ float g_msum_part[NCHUNK*BB*MM];
__device__ float g_dkw[BB*NN];
__device__ float g_dkr[BB*NN];
__device__ float g_n2 [BB*NN];
__device__ float g_dae[BB*NN];
__device__ unsigned g_eadone[BB];           // zero-init; reset each replay by k_mega

__device__ __forceinline__ float lrelu(float v){ return (v>0.f)? v : 0.01f*v; }

// ---- block reductions ----
__device__ __forceinline__ float bredsum(float v, float* sred, int nw){
    const int lane = threadIdx.x & 31, wid = threadIdx.x >> 5;
    #pragma unroll
    for (int o=16;o>0;o>>=1) v += __shfl_xor_sync(0xffffffffu, v, o);
    if (lane==0) sred[wid]=v;
    __syncthreads();
    if (wid==0){
        float w = (lane<nw)? sred[lane] : 0.f;
        #pragma unroll
        for (int o=16;o>0;o>>=1) w += __shfl_xor_sync(0xffffffffu, w, o);
        if (lane==0) sred[0]=w;
    }
    __syncthreads();
    float r = sred[0];
    __syncthreads();
    return r;
}

// ---------------- k1: pass A (pure streaming): n2 + column sums ----------------
__global__ void __launch_bounds__(256) k_passA(const float* __restrict__ bank)
{
    const int u = blockIdx.x;
    const int b = u >> 5, chunk = u & 31;
    const int warp = threadIdx.x >> 5;
    const int lane = threadIdx.x & 31;
    const int sub4 = lane & 3;
    const int rowg = lane >> 2;
    const size_t bbase = (size_t)b * NN;
    const int coff = sub4*4;

    __shared__ float scs[MM];
    if (threadIdx.x < MM) scs[threadIdx.x] = 0.f;

    float4 cs[4];
    #pragma unroll
    for (int i=0;i<4;i++) cs[i] = make_float4(0.f,0.f,0.f,0.f);
    __syncthreads();

    #pragma unroll
    for (int it=0; it<4; it++){
        const int row = chunk*256 + it*64 + warp*8 + rowg;
        const float* rp = bank + (bbase + row)*MM + coff;
        float4 v[4];
        #pragma unroll
        for (int i=0;i<4;i++) v[i] = *reinterpret_cast<const float4*>(rp + i*16);
        float nn = 0.f;
        #pragma unroll
        for (int i=0;i<4;i++){
            nn  = fmaf(v[i].x,v[i].x,nn); nn = fmaf(v[i].y,v[i].y,nn);
            nn  = fmaf(v[i].z,v[i].z,nn); nn = fmaf(v[i].w,v[i].w,nn);
            cs[i].x += v[i].x; cs[i].y += v[i].y; cs[i].z += v[i].z; cs[i].w += v[i].w;
        }
        nn += __shfl_xor_sync(0xffffffffu, nn, 1);
        nn += __shfl_xor_sync(0xffffffffu, nn, 2);
        if (sub4 == 0) g_n2[bbase+row] = nn;
    }
    #pragma unroll
    for (int o=4;o<=16;o<<=1){
        #pragma unroll
        for (int i=0;i<4;i++){
            cs[i].x += __shfl_xor_sync(0xffffffffu, cs[i].x, o);
            cs[i].y += __shfl_xor_sync(0xffffffffu, cs[i].y, o);
            cs[i].z += __shfl_xor_sync(0xffffffffu, cs[i].z, o);
            cs[i].w += __shfl_xor_sync(0xffffffffu, cs[i].w, o);
        }
    }
    if (rowg == 0){
        #pragma unroll
        for (int i=0;i<4;i++){
            atomicAdd(&scs[i*16+coff+0], cs[i].x);
            atomicAdd(&scs[i*16+coff+1], cs[i].y);
            atomicAdd(&scs[i*16+coff+2], cs[i].z);
            atomicAdd(&scs[i*16+coff+3], cs[i].w);
        }
    }
    __syncthreads();
    if (threadIdx.x < MM)
        g_msum_part[(chunk*BB + b)*MM + threadIdx.x] = scs[threadIdx.x];
}

// ---------------- controller + ea body (256 threads, one block per batch) ----------------
__device__ void ctrl_ea_body(int b,
    const float* __restrict__ x,
    const float* __restrict__ W0, const float* __restrict__ b0,
    const float* __restrict__ W1, const float* __restrict__ b1,
    const float* __restrict__ Wc, const float* __restrict__ bc,
    const float* __restrict__ Wr, const float* __restrict__ br,
    const float* __restrict__ Ww, const float* __restrict__ bw,
    const float* __restrict__ Wea, const float* __restrict__ bea,
    const float* __restrict__ wrp, const float* __restrict__ wwp)
{
    const int t = threadIdx.x;
    __shared__ float xs[SEQW+1];
    __shared__ float h0s[HID];
    __shared__ float h1s[HID];
    __shared__ float cs_[OUTC];
    __shared__ float rr[REPR];
    __shared__ float rw[REPR];
    __shared__ float sred[32];
    __shared__ float ma[MM], eas[2*MM];

    if (t < SEQW+1) xs[t] = x[b*(SEQW+1)+t];
    __syncthreads();
    {
        float a0 = b0[t], a1 = b0[t+256];
        #pragma unroll
        for (int i=0;i<SEQW+1;i++){
            float v = xs[i];
            a0 = fmaf(v, W0[i*HID + t],     a0);
            a1 = fmaf(v, W0[i*HID + t+256], a1);
        }
        h0s[t] = lrelu(a0); h0s[t+256] = lrelu(a1);
    }
    __syncthreads();
    {
        float a0 = b1[t], a1 = b1[t+256];
        #pragma unroll 16
        for (int i=0;i<HID;i++){
            float v = h0s[i];
            a0 = fmaf(v, W1[i*HID + t],     a0);
            a1 = fmaf(v, W1[i*HID + t+256], a1);
        }
        h1s[t] = lrelu(a0); h1s[t+256] = lrelu(a1);
    }
    __syncthreads();
    {
        float a0 = bc[t];
        #pragma unroll 16
        for (int i=0;i<HID;i++)
            a0 = fmaf(h1s[i], Wc[i*OUTC + t], a0);
        cs_[t] = lrelu(a0);
    }
    __syncthreads();
    if (t < REPR){
        float a = br[t];
        #pragma unroll 16
        for (int i=0;i<OUTC;i++) a = fmaf(cs_[i], Wr[i*REPR + t], a);
        rr[t] = a;
    } else if (t >= 128 && t < 128+REPR){
        const int j = t-128;
        float a = bw[j];
        #pragma unroll 16
        for (int i=0;i<OUTC;i++) a = fmaf(cs_[i], Ww[i*REPR + j], a);
        rw[j] = a;
    }
    __syncthreads();

    float vr = 0.f, vw = 0.f;
    if (t < MM){
        vr = rr[t]; vw = rw[t];
        g_kr[b*MM+t] = vr; g_kw[b*MM+t] = vw;
    }
    float nr = bredsum(vr*vr, sred, 8);
    float nw_ = bredsum(vw*vw, sred, 8);
    if (t==0){ g_par[b*16+12]=sqrtf(nr); g_par[b*16+13]=sqrtf(nw_); }

    const size_t base = (size_t)b*NN;
    float sr=0.f, sw=0.f;
    for (int n=t; n<NN; n+=256){ sr += wrp[base+n]; sw += wwp[base+n]; }
    sr = bredsum(sr, sred, 8);
    sw = bredsum(sw, sred, 8);
    if (t==0){ g_par[b*16+14]=1.f/sr; g_par[b*16+15]=1.f/sw; }

    if (t==0){
        float* p = &g_par[b*16];
        p[0] = fmaxf(rr[64],0.f)+1e-8f;
        p[1] = 1.f/(1.f+__expf(-rr[65]));
        {
            float m = fmaxf(rr[66], fmaxf(rr[67], rr[68]));
            float e0=__expf(rr[66]-m), e1=__expf(rr[67]-m), e2=__expf(rr[68]-m);
            float s=e0+e1+e2;
            p[2]=e0/s; p[3]=e1/s; p[4]=e2/s;
        }
        p[5] = fmaxf(rr[69],0.f)+1.f;
        p[6] = fmaxf(rw[64],0.f)+1e-8f;
        p[7] = 1.f/(1.f+__expf(-rw[65]));
        {
            float m = fmaxf(rw[66], fmaxf(rw[67], rw[68]));
            float e0=__expf(rw[66]-m), e1=__expf(rw[67]-m), e2=__expf(rw[68]-m);
            float s=e0+e1+e2;
            p[8]=e0/s; p[9]=e1/s; p[10]=e2/s;
        }
        p[11] = fmaxf(rw[69],0.f)+1.f;
    }
    __syncthreads();

    // ---- ea (colsums from k1 are complete; kw/kr in rr/rw smem) ----
    if (t<MM){
        float s = 0.f;
        #pragma unroll 8
        for (int c=0;c<NCHUNK;c++) s += g_msum_part[(c*BB + b)*MM + t];
        ma[t]  = s * (1.f/(float)NN);
    }
    __syncthreads();
    if (t < 2*MM){
        float acc = bea[t];
        #pragma unroll 8
        for (int i=0;i<MM;i++)  acc = fmaf(ma[i], Wea[i*(2*MM)+t],       acc);
        #pragma unroll 8
        for (int i=0;i<MM;i++)  acc = fmaf(rw[i], Wea[(MM+i)*(2*MM)+t],  acc);
        eas[t]=acc;
    }
    __syncthreads();
    float ae=0.f, krv=0.f;
    if (t<MM){
        float e = 1.f/(1.f+__expf(-eas[t]));
        ae = eas[MM+t]-e;
        g_ae[b*MM+t]=ae;
        krv = rr[t];
    }
    float a2 = bredsum(ae*ae, sred, 8);
    float ak = bredsum(ae*krv, sred, 8);
    if (t==0){
        g_aux[b*4+0]=a2; g_aux[b*4+1]=ak;
        __threadfence();
        atomicExch(&g_eadone[b], 1u);
    }
}

// ---------------- k2: ctrl+ea [0,128) + passB REVERSED (spin on ea) ----------------
__global__ void __launch_bounds__(256) k_ctrlB(const float* __restrict__ bank,
    const float* __restrict__ x,
    const float* __restrict__ W0, const float* __restrict__ b0,
    const float* __restrict__ W1, const float* __restrict__ b1,
    const float* __restrict__ Wc, const float* __restrict__ bc,
    const float* __restrict__ Wr, const float* __restrict__ br,
    const float* __restrict__ Ww, const float* __restrict__ bw,
    const float* __restrict__ Wea, const float* __restrict__ bea,
    const float* __restrict__ wrp, const float* __restrict__ wwp)
{
    if (blockIdx.x < BB){
        ctrl_ea_body(blockIdx.x, x, W0,b0, W1,b1, Wc,bc, Wr,br, Ww,bw, Wea,bea, wrp, wwp);
        return;
    }
    // reversed traversal: first blocks read what k1 read LAST (still in L2)
    const int u = (NCHUNK*BB - 1) - (blockIdx.x - BB);
    const int b = u >> 5, chunk = u & 31;
    const int warp = threadIdx.x >> 5;
    const int lane = threadIdx.x & 31;
    const int sub8 = lane & 7;
    const int rowg = lane >> 3;          // 4 rows per warp-iter
    const size_t bbase = (size_t)b * NN;
    const int coff = sub8*8;             // 8 floats per lane

    if (threadIdx.x == 0){
        while (atomicAdd(&g_eadone[b], 0u) == 0u) __nanosleep(200);
    }
    __syncthreads();
    __threadfence();

    const float4 aeA = *reinterpret_cast<const float4*>(&g_ae[b*MM + coff]);
    const float4 aeB = *reinterpret_cast<const float4*>(&g_ae[b*MM + coff + 4]);
    const float4 krA = *reinterpret_cast<const float4*>(&g_kr[b*MM + coff]);
    const float4 krB = *reinterpret_cast<const float4*>(&g_kr[b*MM + coff + 4]);
    const float4 kwA = *reinterpret_cast<const float4*>(&g_kw[b*MM + coff]);
    const float4 kwB = *reinterpret_cast<const float4*>(&g_kw[b*MM + coff + 4]);

    #pragma unroll
    for (int it=0; it<8; it++){
        const int row = chunk*256 + it*32 + warp*4 + rowg;
        const float* rp = bank + (bbase + row)*MM + coff;
        const float4 v0 = *reinterpret_cast<const float4*>(rp);
        const float4 v1 = *reinterpret_cast<const float4*>(rp + 4);
        float dw=0.f, dk=0.f, da=0.f;
        dw=fmaf(v0.x,kwA.x,dw); dw=fmaf(v0.y,kwA.y,dw); dw=fmaf(v0.z,kwA.z,dw); dw=fmaf(v0.w,kwA.w,dw);
        dw=fmaf(v1.x,kwB.x,dw); dw=fmaf(v1.y,kwB.y,dw); dw=fmaf(v1.z,kwB.z,dw); dw=fmaf(v1.w,kwB.w,dw);
        dk=fmaf(v0.x,krA.x,dk); dk=fmaf(v0.y,krA.y,dk); dk=fmaf(v0.z,krA.z,dk); dk=fmaf(v0.w,krA.w,dk);
        dk=fmaf(v1.x,krB.x,dk); dk=fmaf(v1.y,krB.y,dk); dk=fmaf(v1.z,krB.z,dk); dk=fmaf(v1.w,krB.w,dk);
        da=fmaf(v0.x,aeA.x,da); da=fmaf(v0.y,aeA.y,da); da=fmaf(v0.z,aeA.z,da); da=fmaf(v0.w,aeA.w,da);
        da=fmaf(v1.x,aeB.x,da); da=fmaf(v1.y,aeB.y,da); da=fmaf(v1.z,aeB.z,da); da=fmaf(v1.w,aeB.w,da);
        #pragma unroll
        for (int o=1;o<8;o<<=1){
            dw += __shfl_xor_sync(0xffffffffu, dw, o);
            dk += __shfl_xor_sync(0xffffffffu, dk, o);
            da += __shfl_xor_sync(0xffffffffu, da, o);
        }
        if (sub8 == 0){
            g_dkw[bbase+row] = dw;
            g_dkr[bbase+row] = dk;
            g_dae[bbase+row] = da;
        }
    }
}

// ---------------- k3: MEGA — addrW + addrR + weighted read + final head ----------------
__global__ void __launch_bounds__(1024) k_mega(const float* __restrict__ bank,
                                               const float* __restrict__ wwp,
                                               const float* __restrict__ wrp,
                                               const float* __restrict__ Wsp,
                                               const float* __restrict__ bsp,
                                               const float* __restrict__ Wo,
                                               const float* __restrict__ bo,
                                               float* __restrict__ out)
{
    __shared__ float arr[NN];       // wg scratch, then wr
    __shared__ float sred[32];
    __shared__ float scs[MM];
    __shared__ float om[MM];
    __shared__ float seq[HID];
    const int b = blockIdx.x;
    const int t = threadIdx.x;
    if (t==0) g_eadone[b] = 0u;     // reset for next graph replay
    if (t<MM) scs[t] = 0.f;
    const size_t base = (size_t)b*NN;
    const float* p = &g_par[b*16];

    float ww_loc[8];
    float S;

    // ======= WRITE addressing (softmax shifted by beta: cos<=1 so exp arg <=0) =======
    {
        const float beta=p[6], gg=p[7], s0=p[8], s1=p[9], s2=p[10], gamma=p[11];
        const float nk=p[13], invs=p[15];
        float lsum=0.f;
        #pragma unroll
        for (int i=0;i<8;i++){
            int n = t + i*1024;
            float cosv = __fdividef(g_dkw[base+n], fmaxf(sqrtf(g_n2[base+n])*nk, 1e-8f));
            float e = __expf(beta*cosv - beta);
            arr[n]=e; lsum+=e;
        }
        const float invsum = __fdividef(1.f, bredsum(lsum, sred, 32));
        #pragma unroll
        for (int i=0;i<8;i++){
            int n=t+i*1024;
            float wc  = arr[n]*invsum;
            arr[n] = gg*wc + (1.f-gg)*wwp[base+n]*invs;
        }
        __syncthreads();
        float lps=0.f;
        #pragma unroll
        for (int i=0;i<8;i++){
            int n=t+i*1024;
            float ws = s0*arr[(n+NN-1)&(NN-1)] + s1*arr[n] + s2*arr[(n+1)&(NN-1)];
            float wp = __powf(ws, gamma);
            ww_loc[i]=wp; lps+=wp;
        }
        const float invp = __fdividef(1.f, bredsum(lps, sred, 32));
        #pragma unroll
        for (int i=0;i<8;i++) ww_loc[i] *= invp;
    }
    __syncthreads();   // arr reuse barrier

    // ======= READ addressing (virtual new_bank via rank-1 algebra) =======
    {
        const float beta=p[0], gg=p[1], s0=p[2], s1=p[3], s2=p[4], gamma=p[5];
        const float nk=p[12], invs=p[14];
        const float ae2=g_aux[b*4], aekr=g_aux[b*4+1];
        float lsum=0.f;
        #pragma unroll
        for (int i=0;i<8;i++){
            int n = t + i*1024;
            float w  = ww_loc[i];
            float d  = g_dkr[base+n] + w*aekr;
            float nn = fmaxf(g_n2[base+n] + 2.f*w*g_dae[base+n] + w*w*ae2, 0.f);
            float cosv = __fdividef(d, fmaxf(sqrtf(nn)*nk, 1e-8f));
            float e = __expf(beta*cosv - beta);
            arr[n]=e; lsum+=e;
        }
        const float invsum = __fdividef(1.f, bredsum(lsum, sred, 32));
        #pragma unroll
        for (int i=0;i<8;i++){
            int n=t+i*1024;
            float wc  = arr[n]*invsum;
            arr[n] = gg*wc + (1.f-gg)*wrp[base+n]*invs;
        }
        __syncthreads();
        float wp_loc[8];
        float lps=0.f;
        #pragma unroll
        for (int i=0;i<8;i++){
            int n=t+i*1024;
            float ws = s0*arr[(n+NN-1)&(NN-1)] + s1*arr[n] + s2*arr[(n+1)&(NN-1)];
            float wp = __powf(ws, gamma);
            wp_loc[i]=wp; lps+=wp;
        }
        const float invp = __fdividef(1.f, bredsum(lps, sred, 32));   // barrier: shift reads done
        float lS=0.f;
        #pragma unroll
        for (int i=0;i<8;i++){
            int n=t+i*1024;
            float w = wp_loc[i]*invp;
            arr[n] = w;                 // arr now holds w_r
            lS += ww_loc[i]*w;
        }
        S = bredsum(lS, sred, 32);      // barrier: arr writes visible
    }

    // ======= Weighted read: out_raw[m] = sum_n bank[b,n,m] * wr[n] =======
    {
        const int lane = t & 31;
        const int warp = t >> 5;         // 32 warps
        const int sub16 = lane & 15;
        const int half = lane >> 4;
        float4 acc = make_float4(0.f,0.f,0.f,0.f);
        const float* bp = bank + base*MM + sub16*4;

        #pragma unroll 1
        for (int it=0; it<32; it++){
            float4 v[4]; float w4[4]; int row[4];
            #pragma unroll
            for (int j=0;j<4;j++){
                row[j] = (it*4+j)*64 + warp*2 + half;
                v[j] = *reinterpret_cast<const float4*>(bp + (size_t)row[j]*MM);
                w4[j] = arr[row[j]];
            }
            #pragma unroll
            for (int j=0;j<4;j++){
                acc.x = fmaf(v[j].x, w4[j], acc.x);
                acc.y = fmaf(v[j].y, w4[j], acc.y);
                acc.z = fmaf(v[j].z, w4[j], acc.z);
                acc.w = fmaf(v[j].w, w4[j], acc.w);
            }
        }
        acc.x += __shfl_xor_sync(0xffffffffu, acc.x, 16);
        acc.y += __shfl_xor_sync(0xffffffffu, acc.y, 16);
        acc.z += __shfl_xor_sync(0xffffffffu, acc.z, 16);
        acc.w += __shfl_xor_sync(0xffffffffu, acc.w, 16);
        if (half == 0){
            atomicAdd(&scs[sub16*4+0], acc.x);
            atomicAdd(&scs[sub16*4+1], acc.y);
            atomicAdd(&scs[sub16*4+2], acc.z);
            atomicAdd(&scs[sub16*4+3], acc.w);
        }
        __syncthreads();
    }

    // ======= final head =======
    if (t<MM) om[t] = scs[t] + S*g_ae[b*MM+t];
    __syncthreads();
    if (t<HID){
        float a = bsp[t];
        #pragma unroll 8
        for (int i=0;i<MM;i++) a = fmaf(om[i], Wsp[i*HID+t], a);
        seq[t] = lrelu(a);
    }
    __syncthreads();
    if (t<SEQW){
        float a = bo[t];
        for (int i=0;i<HID;i++) a = fmaf(seq[i], Wo[i*SEQW+t], a);
        out[b*SEQW+t] = 1.f/(1.f+__expf(-a));
    }
}

// ---------------- launch ----------------
extern "C" void kernel_launch(void* const* d_in, const int* in_sizes, int n_in,
                              void* d_out, int out_size)
{
    const float* x    = (const float*)d_in[0];
    const float* bank = (const float*)d_in[1];
    const float* wrp  = (const float*)d_in[2];
    const float* wwp  = (const float*)d_in[3];
    const float* W0   = (const float*)d_in[4];
    const float* b0   = (const float*)d_in[5];
    const float* W1   = (const float*)d_in[6];
    const float* b1   = (const float*)d_in[7];
    const float* Wc   = (const float*)d_in[8];
    const float* bc   = (const float*)d_in[9];
    const float* Wr   = (const float*)d_in[10];
    const float* br   = (const float*)d_in[11];
    const float* Ww   = (const float*)d_in[12];
    const float* bw   = (const float*)d_in[13];
    const float* Wea  = (const float*)d_in[14];
    const float* bea  = (const float*)d_in[15];
    const float* Wsp  = (const float*)d_in[16];
    const float* bsp  = (const float*)d_in[17];
    const float* Wo   = (const float*)d_in[18];
    const float* bo   = (const float*)d_in[19];
    float* out = (float*)d_out;

    k_passA<<<NCHUNK*BB, 256>>>(bank);                    // pure streaming: n2 + colsums
    k_ctrlB<<<BB + NCHUNK*BB, 256>>>(bank, x, W0,b0, W1,b1, Wc,bc, Wr,br, Ww,bw,
                                     Wea,bea, wrp, wwp);  // ctrl+ea + passB (reversed)
    k_mega<<<BB, 1024>>>(bank, wwp, wrp, Wsp, bsp, Wo, bo, out);
}

// round 13
// speedup vs baseline: 1.5818x; 1.2047x over previous
#include <cuda_runtime.h>
#include <math.h>

#define BB   128
#define NN   8192
#define MM   64
#define HID  512
#define OUTC 256
#define REPR 70
#define SEQW 63
#define SMEM_DYN (4*NN*sizeof(float))   // n2, dkw, dkr, dae : 128 KB

#define NB() asm volatile("bar.sync 1, 256;" ::: "memory")

__device__ __forceinline__ float lrelu(float v){ return (v>0.f)? v : 0.01f*v; }

// block-wide sum, 1024 threads (32 warps)
__device__ __forceinline__ float bredsum1024(float v, float* sred){
    const int lane = threadIdx.x & 31, wid = threadIdx.x >> 5;
    #pragma unroll
    for (int o=16;o>0;o>>=1) v += __shfl_xor_sync(0xffffffffu, v, o);
    if (lane==0) sred[wid]=v;
    __syncthreads();
    if (wid==0){
        float w = sred[lane];
        #pragma unroll
        for (int o=16;o>0;o>>=1) w += __shfl_xor_sync(0xffffffffu, w, o);
        if (lane==0) sred[0]=w;
    }
    __syncthreads();
    float r = sred[0];
    __syncthreads();
    return r;
}

// ctrl-group (first 256 threads) sum via named barrier 1
__device__ __forceinline__ float credsum256(float v, float* cred){
    const int lane = threadIdx.x & 31, wid = threadIdx.x >> 5;  // wid 0..7
    #pragma unroll
    for (int o=16;o>0;o>>=1) v += __shfl_xor_sync(0xffffffffu, v, o);
    if (lane==0) cred[wid]=v;
    NB();
    float r = cred[0]+cred[1]+cred[2]+cred[3]+cred[4]+cred[5]+cred[6]+cred[7];
    NB();
    return r;
}

// ---------------- THE kernel: one block per batch, everything fused ----------------
__global__ void __launch_bounds__(1024) k_mega(
    const float* __restrict__ bank,
    const float* __restrict__ x,
    const float* __restrict__ wrp, const float* __restrict__ wwp,
    const float* __restrict__ W0, const float* __restrict__ b0,
    const float* __restrict__ W1, const float* __restrict__ b1,
    const float* __restrict__ Wc, const float* __restrict__ bc,
    const float* __restrict__ Wr, const float* __restrict__ br,
    const float* __restrict__ Ww, const float* __restrict__ bw,
    const float* __restrict__ Wea, const float* __restrict__ bea,
    const float* __restrict__ Wsp, const float* __restrict__ bsp,
    const float* __restrict__ Wo,  const float* __restrict__ bo,
    float* __restrict__ out)
{
    extern __shared__ float sm[];
    float* s_n2  = sm;
    float* s_dkw = sm + NN;
    float* s_dkr = sm + 2*NN;
    float* s_dae = sm + 3*NN;

    __shared__ float xs[SEQW+1], h0s[HID], h1s[HID], cs_[OUTC];
    __shared__ float rr[REPR], rw[REPR];
    __shared__ float sred[32], cred[8], scs[MM], om[MM], seqs[HID];
    __shared__ float s_kw[MM], s_kr[MM], s_ae[MM], pp[16];
    __shared__ float ma[MM], eas[2*MM];

    const int b = blockIdx.x;
    const int t = threadIdx.x;
    const int lane = t & 31, wid = t >> 5;
    const size_t base = (size_t)b * NN;

    if (t < MM) scs[t] = 0.f;
    __syncthreads();

    // ===================== Phase A: ctrl (t<256) || colsum (t>=256) =====================
    if (t < 256){
        if (t < SEQW+1) xs[t] = x[b*(SEQW+1)+t];
        NB();
        {   // layer 0: 64 -> 512
            float a0 = b0[t], a1 = b0[t+256];
            #pragma unroll
            for (int i=0;i<SEQW+1;i++){
                float v = xs[i];
                a0 = fmaf(v, W0[i*HID + t],     a0);
                a1 = fmaf(v, W0[i*HID + t+256], a1);
            }
            h0s[t] = lrelu(a0); h0s[t+256] = lrelu(a1);
        }
        NB();
        {   // layer 1: 512 -> 512
            float a0 = b1[t], a1 = b1[t+256];
            #pragma unroll 16
            for (int i=0;i<HID;i++){
                float v = h0s[i];
                a0 = fmaf(v, W1[i*HID + t],     a0);
                a1 = fmaf(v, W1[i*HID + t+256], a1);
            }
            h1s[t] = lrelu(a0); h1s[t+256] = lrelu(a1);
        }
        NB();
        {   // ctrl: 512 -> 256
            float a0 = bc[t];
            #pragma unroll 16
            for (int i=0;i<HID;i++)
                a0 = fmaf(h1s[i], Wc[i*OUTC + t], a0);
            cs_[t] = lrelu(a0);
        }
        NB();
        if (t < REPR){
            float a = br[t];
            #pragma unroll 16
            for (int i=0;i<OUTC;i++) a = fmaf(cs_[i], Wr[i*REPR + t], a);
            rr[t] = a;
        } else if (t >= 128 && t < 128+REPR){
            const int j = t-128;
            float a = bw[j];
            #pragma unroll 16
            for (int i=0;i<OUTC;i++) a = fmaf(cs_[i], Ww[i*REPR + j], a);
            rw[j] = a;
        }
        NB();
        float vr = 0.f, vw = 0.f;
        if (t < MM){
            vr = rr[t]; vw = rw[t];
            s_kr[t] = vr; s_kw[t] = vw;
        }
        float nr  = credsum256(vr*vr, cred);
        float nw_ = credsum256(vw*vw, cred);
        float sr=0.f, sw=0.f;
        for (int n=t; n<NN; n+=256){ sr += wrp[base+n]; sw += wwp[base+n]; }
        sr = credsum256(sr, cred);
        sw = credsum256(sw, cred);
        if (t==0){
            pp[12]=sqrtf(nr); pp[13]=sqrtf(nw_);
            pp[14]=1.f/sr;    pp[15]=1.f/sw;
            pp[0] = fmaxf(rr[64],0.f)+1e-8f;
            pp[1] = 1.f/(1.f+__expf(-rr[65]));
            {
                float m = fmaxf(rr[66], fmaxf(rr[67], rr[68]));
                float e0=__expf(rr[66]-m), e1=__expf(rr[67]-m), e2=__expf(rr[68]-m);
                float s=e0+e1+e2;
                pp[2]=e0/s; pp[3]=e1/s; pp[4]=e2/s;
            }
            pp[5] = fmaxf(rr[69],0.f)+1.f;
            pp[6] = fmaxf(rw[64],0.f)+1e-8f;
            pp[7] = 1.f/(1.f+__expf(-rw[65]));
            {
                float m = fmaxf(rw[66], fmaxf(rw[67], rw[68]));
                float e0=__expf(rw[66]-m), e1=__expf(rw[67]-m), e2=__expf(rw[68]-m);
                float s=e0+e1+e2;
                pp[8]=e0/s; pp[9]=e1/s; pp[10]=e2/s;
            }
            pp[11] = fmaxf(rw[69],0.f)+1.f;
        }
    } else {
        // colsum with 768 threads (warps 8..31)
        const int wc2 = wid - 8;            // 0..23
        const int sub16 = lane & 15, half = lane >> 4;
        const float* bp = bank + base*MM + sub16*4;
        float4 cs = make_float4(0.f,0.f,0.f,0.f);
        for (int it=0; it<43; it++){
            #pragma unroll
            for (int j=0;j<4;j++){
                int row = (it*4+j)*48 + wc2*2 + half;
                if (row < NN){
                    float4 v = *reinterpret_cast<const float4*>(bp + (size_t)row*MM);
                    cs.x += v.x; cs.y += v.y; cs.z += v.z; cs.w += v.w;
                }
            }
        }
        cs.x += __shfl_xor_sync(0xffffffffu, cs.x, 16);
        cs.y += __shfl_xor_sync(0xffffffffu, cs.y, 16);
        cs.z += __shfl_xor_sync(0xffffffffu, cs.z, 16);
        cs.w += __shfl_xor_sync(0xffffffffu, cs.w, 16);
        if (half == 0){
            atomicAdd(&scs[sub16*4+0], cs.x);
            atomicAdd(&scs[sub16*4+1], cs.y);
            atomicAdd(&scs[sub16*4+2], cs.z);
            atomicAdd(&scs[sub16*4+3], cs.w);
        }
    }
    __syncthreads();

    // ===================== ea =====================
    if (t < MM) ma[t] = scs[t] * (1.f/(float)NN);
    __syncthreads();
    if (t < MM) scs[t] = 0.f;     // re-zero for the weighted-read phase
    if (t < 2*MM){
        float acc = bea[t];
        #pragma unroll 8
        for (int i=0;i<MM;i++) acc = fmaf(ma[i],   Wea[i*(2*MM)+t],      acc);
        #pragma unroll 8
        for (int i=0;i<MM;i++) acc = fmaf(s_kw[i], Wea[(MM+i)*(2*MM)+t], acc);
        eas[t] = acc;
    }
    __syncthreads();
    float aev = 0.f, krv = 0.f;
    if (t < MM){
        float e = 1.f/(1.f+__expf(-eas[t]));
        aev = eas[MM+t]-e;
        s_ae[t] = aev;
        krv = s_kr[t];
    }
    const float ae2  = bredsum1024(aev*aev,  sred);
    const float aekr = bredsum1024(aev*krv, sred);

    // ===================== Phase 1: one stream -> n2, dkw, dkr, dae (smem) =====================
    {
        const int sub8 = lane & 7, rowg = lane >> 3;
        const int coff = sub8*8;
        const float4 kwA = *reinterpret_cast<const float4*>(&s_kw[coff]);
        const float4 kwB = *reinterpret_cast<const float4*>(&s_kw[coff+4]);
        const float4 krA = *reinterpret_cast<const float4*>(&s_kr[coff]);
        const float4 krB = *reinterpret_cast<const float4*>(&s_kr[coff+4]);
        const float4 aeA = *reinterpret_cast<const float4*>(&s_ae[coff]);
        const float4 aeB = *reinterpret_cast<const float4*>(&s_ae[coff+4]);
        const float* bp = bank + base*MM + coff;
        for (int r0=0; r0<64; r0++){
            const int row = r0*128 + wid*4 + rowg;
            const float4 v0 = *reinterpret_cast<const float4*>(bp + (size_t)row*MM);
            const float4 v1 = *reinterpret_cast<const float4*>(bp + (size_t)row*MM + 4);
            float dw=0.f, dk=0.f, da=0.f, nn=0.f;
            dw=fmaf(v0.x,kwA.x,dw); dw=fmaf(v0.y,kwA.y,dw); dw=fmaf(v0.z,kwA.z,dw); dw=fmaf(v0.w,kwA.w,dw);
            dw=fmaf(v1.x,kwB.x,dw); dw=fmaf(v1.y,kwB.y,dw); dw=fmaf(v1.z,kwB.z,dw); dw=fmaf(v1.w,kwB.w,dw);
            dk=fmaf(v0.x,krA.x,dk); dk=fmaf(v0.y,krA.y,dk); dk=fmaf(v0.z,krA.z,dk); dk=fmaf(v0.w,krA.w,dk);
            dk=fmaf(v1.x,krB.x,dk); dk=fmaf(v1.y,krB.y,dk); dk=fmaf(v1.z,krB.z,dk); dk=fmaf(v1.w,krB.w,dk);
            da=fmaf(v0.x,aeA.x,da); da=fmaf(v0.y,aeA.y,da); da=fmaf(v0.z,aeA.z,da); da=fmaf(v0.w,aeA.w,da);
            da=fmaf(v1.x,aeB.x,da); da=fmaf(v1.y,aeB.y,da); da=fmaf(v1.z,aeB.z,da); da=fmaf(v1.w,aeB.w,da);
            nn=fmaf(v0.x,v0.x,nn);  nn=fmaf(v0.y,v0.y,nn);  nn=fmaf(v0.z,v0.z,nn);  nn=fmaf(v0.w,v0.w,nn);
            nn=fmaf(v1.x,v1.x,nn);  nn=fmaf(v1.y,v1.y,nn);  nn=fmaf(v1.z,v1.z,nn);  nn=fmaf(v1.w,v1.w,nn);
            #pragma unroll
            for (int o=1;o<8;o<<=1){
                dw += __shfl_xor_sync(0xffffffffu, dw, o);
                dk += __shfl_xor_sync(0xffffffffu, dk, o);
                da += __shfl_xor_sync(0xffffffffu, da, o);
                nn += __shfl_xor_sync(0xffffffffu, nn, o);
            }
            if (sub8 == 0){
                s_dkw[row]=dw; s_dkr[row]=dk; s_dae[row]=da; s_n2[row]=nn;
            }
        }
    }
    __syncthreads();

    float ww_loc[8];
    float S;

    // ===================== write addressing (in s_dkw, shifted softmax) =====================
    {
        const float beta=pp[6], gg=pp[7], s0=pp[8], s1=pp[9], s2=pp[10], gamma=pp[11];
        const float nk=pp[13], invs=pp[15];
        float lsum=0.f;
        #pragma unroll
        for (int i=0;i<8;i++){
            int n = t + i*1024;
            float cosv = __fdividef(s_dkw[n], fmaxf(sqrtf(s_n2[n])*nk, 1e-8f));
            float e = __expf(beta*cosv - beta);
            s_dkw[n]=e; lsum+=e;
        }
        const float invsum = __fdividef(1.f, bredsum1024(lsum, sred));
        #pragma unroll
        for (int i=0;i<8;i++){
            int n=t+i*1024;
            float wc = s_dkw[n]*invsum;
            s_dkw[n] = gg*wc + (1.f-gg)*wwp[base+n]*invs;
        }
        __syncthreads();
        float lps=0.f;
        #pragma unroll
        for (int i=0;i<8;i++){
            int n=t+i*1024;
            float ws = s0*s_dkw[(n+NN-1)&(NN-1)] + s1*s_dkw[n] + s2*s_dkw[(n+1)&(NN-1)];
            float wp = __powf(ws, gamma);
            ww_loc[i]=wp; lps+=wp;
        }
        const float invp = __fdividef(1.f, bredsum1024(lps, sred));
        #pragma unroll
        for (int i=0;i<8;i++) ww_loc[i] *= invp;
    }

    // ===================== read addressing (in s_dkr; rank-1 new_bank algebra) =====================
    {
        const float beta=pp[0], gg=pp[1], s0=pp[2], s1=pp[3], s2=pp[4], gamma=pp[5];
        const float nk=pp[12], invs=pp[14];
        float lsum=0.f;
        #pragma unroll
        for (int i=0;i<8;i++){
            int n = t + i*1024;
            float w  = ww_loc[i];
            float d  = s_dkr[n] + w*aekr;
            float nn = fmaxf(s_n2[n] + 2.f*w*s_dae[n] + w*w*ae2, 0.f);
            float cosv = __fdividef(d, fmaxf(sqrtf(nn)*nk, 1e-8f));
            float e = __expf(beta*cosv - beta);
            s_dkr[n]=e; lsum+=e;
        }
        const float invsum = __fdividef(1.f, bredsum1024(lsum, sred));
        #pragma unroll
        for (int i=0;i<8;i++){
            int n=t+i*1024;
            float wc = s_dkr[n]*invsum;
            s_dkr[n] = gg*wc + (1.f-gg)*wrp[base+n]*invs;
        }
        __syncthreads();
        float wp_loc[8];
        float lps=0.f;
        #pragma unroll
        for (int i=0;i<8;i++){
            int n=t+i*1024;
            float ws = s0*s_dkr[(n+NN-1)&(NN-1)] + s1*s_dkr[n] + s2*s_dkr[(n+1)&(NN-1)];
            float wp = __powf(ws, gamma);
            wp_loc[i]=wp; lps+=wp;
        }
        const float invp = __fdividef(1.f, bredsum1024(lps, sred));  // barrier: shift reads done
        float lS=0.f;
        #pragma unroll
        for (int i=0;i<8;i++){
            int n=t+i*1024;
            float w = wp_loc[i]*invp;
            s_dkr[n] = w;                 // s_dkr now holds w_r
            lS += ww_loc[i]*w;
        }
        S = bredsum1024(lS, sred);        // barrier: w_r visible
    }

    // ===================== weighted read =====================
    {
        const int sub16 = lane & 15;
        const int half = lane >> 4;
        float4 acc = make_float4(0.f,0.f,0.f,0.f);
        const float* bp = bank + base*MM + sub16*4;
        #pragma unroll 1
        for (int it=0; it<32; it++){
            float4 v[4]; float w4[4]; int row[4];
            #pragma unroll
            for (int j=0;j<4;j++){
                row[j] = (it*4+j)*64 + wid*2 + half;
                v[j] = *reinterpret_cast<const float4*>(bp + (size_t)row[j]*MM);
                w4[j] = s_dkr[row[j]];
            }
            #pragma unroll
            for (int j=0;j<4;j++){
                acc.x = fmaf(v[j].x, w4[j], acc.x);
                acc.y = fmaf(v[j].y, w4[j], acc.y);
                acc.z = fmaf(v[j].z, w4[j], acc.z);
                acc.w = fmaf(v[j].w, w4[j], acc.w);
            }
        }
        acc.x += __shfl_xor_sync(0xffffffffu, acc.x, 16);
        acc.y += __shfl_xor_sync(0xffffffffu, acc.y, 16);
        acc.z += __shfl_xor_sync(0xffffffffu, acc.z, 16);
        acc.w += __shfl_xor_sync(0xffffffffu, acc.w, 16);
        if (half == 0){
            atomicAdd(&scs[sub16*4+0], acc.x);
            atomicAdd(&scs[sub16*4+1], acc.y);
            atomicAdd(&scs[sub16*4+2], acc.z);
            atomicAdd(&scs[sub16*4+3], acc.w);
        }
        __syncthreads();
    }

    // ===================== final head =====================
    if (t < MM) om[t] = scs[t] + S*s_ae[t];
    __syncthreads();
    if (t < HID){
        float a = bsp[t];
        #pragma unroll 8
        for (int i=0;i<MM;i++) a = fmaf(om[i], Wsp[i*HID+t], a);
        seqs[t] = lrelu(a);
    }
    __syncthreads();
    if (t < SEQW){
        float a = bo[t];
        for (int i=0;i<HID;i++) a = fmaf(seqs[i], Wo[i*SEQW+t], a);
        out[b*SEQW+t] = 1.f/(1.f+__expf(-a));
    }
}

// ---------------- launch ----------------
extern "C" void kernel_launch(void* const* d_in, const int* in_sizes, int n_in,
                              void* d_out, int out_size)
{
    const float* x    = (const float*)d_in[0];
    const float* bank = (const float*)d_in[1];
    const float* wrp  = (const float*)d_in[2];
    const float* wwp  = (const float*)d_in[3];
    const float* W0   = (const float*)d_in[4];
    const float* b0   = (const float*)d_in[5];
    const float* W1   = (const float*)d_in[6];
    const float* b1   = (const float*)d_in[7];
    const float* Wc   = (const float*)d_in[8];
    const float* bc   = (const float*)d_in[9];
    const float* Wr   = (const float*)d_in[10];
    const float* br   = (const float*)d_in[11];
    const float* Ww   = (const float*)d_in[12];
    const float* bw   = (const float*)d_in[13];
    const float* Wea  = (const float*)d_in[14];
    const float* bea  = (const float*)d_in[15];
    const float* Wsp  = (const float*)d_in[16];
    const float* bsp  = (const float*)d_in[17];
    const float* Wo   = (const float*)d_in[18];
    const float* bo   = (const float*)d_in[19];
    float* out = (float*)d_out;

    cudaFuncSetAttribute(k_mega, cudaFuncAttributeMaxDynamicSharedMemorySize,
                         (int)SMEM_DYN);
    k_mega<<<BB, 1024, SMEM_DYN>>>(bank, x, wrp, wwp,
                                   W0,b0, W1,b1, Wc,bc, Wr,br, Ww,bw,
                                   Wea,bea, Wsp,bsp, Wo,bo, out);
}